// round 8
// baseline (speedup 1.0000x reference)
#include <cuda_runtime.h>
#include <cuda_bf16.h>
#include <cstdint>
#include <cstddef>

// ---------------------------------------------------------------------------
// Problem constants
// ---------------------------------------------------------------------------
#define BATCH   256
#define NPTS    1024
#define HID     256
#define ACT     6
#define GRU_BLOCKS 128

// device scratch
__device__ float g_feat[BATCH * 512];
__device__ float g_h[BATCH * HID];          // GRU hidden state (live)
__device__ float g_gh[BATCH * 768];         // per-step gh results
__device__ float g_WhhT[HID * 768];         // W_hh transposed [k][j]
__device__ unsigned g_W3tf[4 * 128 * 128];  // tf32 image, [nc][k][n]
__device__ int g_barA[GRU_BLOCKS];
__device__ int g_barB[GRU_BLOCKS];

// ---------------------------------------------------------------------------
// helpers
// ---------------------------------------------------------------------------
__device__ __forceinline__ unsigned f2tf(float x) {
    unsigned u; asm("cvt.rna.tf32.f32 %0, %1;" : "=r"(u) : "f"(x)); return u;
}

__device__ __forceinline__ void mma_tf32(float* d, const unsigned* a, const unsigned* b) {
    asm volatile(
        "mma.sync.aligned.m16n8k8.row.col.f32.tf32.tf32.f32 "
        "{%0,%1,%2,%3}, {%4,%5,%6,%7}, {%8,%9}, {%0,%1,%2,%3};\n"
        : "+f"(d[0]), "+f"(d[1]), "+f"(d[2]), "+f"(d[3])
        : "r"(a[0]), "r"(a[1]), "r"(a[2]), "r"(a[3]), "r"(b[0]), "r"(b[1]));
}

#define FMA2(d, a, b) asm volatile("fma.rn.f32x2 %0, %1, %2, %0;" : "+l"(d) : "l"(a), "l"(b))
typedef unsigned long long ull;

__device__ __forceinline__ float sigf(float x) { return 1.f / (1.f + __expf(-x)); }
__device__ __forceinline__ float tanhfast(float x) { return 2.f / (1.f + __expf(-2.f * x)) - 1.f; }

// ---------------------------------------------------------------------------
// prep kernels
// ---------------------------------------------------------------------------
__global__ void zero_feat_kernel() {
    g_feat[blockIdx.x * 256 + threadIdx.x] = 0.f;
}

__global__ void transpose_whh_kernel(const float* __restrict__ Whh) {
    int idx = blockIdx.x * 256 + threadIdx.x;
    int k = idx / 768, j = idx - k * 768;
    g_WhhT[idx] = Whh[j * 256 + k];
}

__global__ void zero_flags_kernel() {
    if (threadIdx.x < GRU_BLOCKS) { g_barA[threadIdx.x] = 0; g_barB[threadIdx.x] = 0; }
}

// W3 [128k][512n] -> tf32 image [nc][k][n(128)]
__global__ void prep_w3_kernel(const float* __restrict__ w3) {
    int idx = blockIdx.x * 256 + threadIdx.x;
    int nc = idx >> 14, r = idx & 16383;
    int k = r >> 7, n = r & 127;
    g_W3tf[idx] = f2tf(w3[(size_t)k * 512 + nc * 128 + n]);
}

// ---------------------------------------------------------------------------
// Fused PointNet encoder (identical to R7 passing version)
// ---------------------------------------------------------------------------
#define ENC_HP_LD 132
#define ENC_SW_LD 136
#define ENC_SMEM_FLOATS (16896 + 17920)

__global__ void __launch_bounds__(512) enc_kernel(
    const float* __restrict__ data,
    const float* __restrict__ w1, const float* __restrict__ b1,
    const float* __restrict__ w2, const float* __restrict__ b2,
    const float* __restrict__ b3)
{
    extern __shared__ float sm[];
    float* Hp   = sm;
    float* work = sm + 16896;
    float* rA   = work;
    float* sW   = work;
    float* sRed = work + 17408;
    __shared__ float sPts[128 * 3];

    const int tid   = threadIdx.x;
    const int b     = blockIdx.y;
    const int chunk = blockIdx.x;

    const float* dptr = data + (size_t)(b * NPTS + chunk * 128) * 3;
    if (tid < 384) sPts[tid] = dptr[tid];
    for (int i = tid * 4; i < 8192; i += 2048)
        *(float4*)(rA + 8192 + i) = *(const float4*)(w2 + i);
    __syncthreads();

    #pragma unroll
    for (int it = 0; it < 16; ++it) {
        int idx = tid + it * 512;
        int k = idx >> 7, i = idx & 127;
        float v = b1[k] + sPts[i*3] * w1[k] + sPts[i*3+1] * w1[64 + k] + sPts[i*3+2] * w1[128 + k];
        rA[idx] = fmaxf(v, 0.f);
    }
    __syncthreads();

    {
        const int i0 = (tid >> 5) * 8;
        const int j0 = (tid & 31) * 4;
        float acc[8][4];
        #pragma unroll
        for (int a = 0; a < 8; ++a)
            #pragma unroll
            for (int c = 0; c < 4; ++c) acc[a][c] = 0.f;

        #pragma unroll 4
        for (int k = 0; k < 64; ++k) {
            float av[8], wv[4];
            *(float4*)&av[0] = *(float4*)(rA + k*128 + i0);
            *(float4*)&av[4] = *(float4*)(rA + k*128 + i0 + 4);
            *(float4*)&wv[0] = *(float4*)(rA + 8192 + k*128 + j0);
            #pragma unroll
            for (int a = 0; a < 8; ++a)
                #pragma unroll
                for (int c = 0; c < 4; ++c) acc[a][c] += av[a] * wv[c];
        }
        float bj[4];
        #pragma unroll
        for (int c = 0; c < 4; ++c) bj[c] = b2[j0 + c];
        unsigned* Hpu = (unsigned*)Hp;
        #pragma unroll
        for (int a = 0; a < 8; ++a) {
            unsigned uv[4];
            #pragma unroll
            for (int c = 0; c < 4; ++c)
                uv[c] = f2tf(fmaxf(acc[a][c] + bj[c], 0.f));
            *(uint4*)(Hpu + (i0 + a) * ENC_HP_LD + j0) = make_uint4(uv[0], uv[1], uv[2], uv[3]);
        }
    }
    __syncthreads();

    const int lane = tid & 31, wrp = tid >> 5;
    const int wm = wrp & 3, wn = wrp >> 2;
    const int qp = lane >> 2, rr = lane & 3;
    const unsigned* Hpu = (const unsigned*)Hp;
    unsigned* sWu = (unsigned*)sW;

    for (int nc = 0; nc < 4; ++nc) {
        {
            const float* src = (const float*)(g_W3tf + nc * 16384);
            for (int i = tid * 4; i < 16384; i += 2048) {
                int k = i >> 7, n = i & 127;
                *(float4*)(sW + k * ENC_SW_LD + n) = *(const float4*)(src + i);
            }
        }
        __syncthreads();

        float acc[2][4][4];
        #pragma unroll
        for (int mt = 0; mt < 2; ++mt)
            #pragma unroll
            for (int nt = 0; nt < 4; ++nt)
                #pragma unroll
                for (int q = 0; q < 4; ++q) acc[mt][nt][q] = 0.f;

        #pragma unroll 1
        for (int ks = 0; ks < 16; ++ks) {
            int k0 = ks * 8;
            unsigned af[2][4];
            #pragma unroll
            for (int mt = 0; mt < 2; ++mt) {
                int r0 = wm * 32 + mt * 16 + qp;
                af[mt][0] = Hpu[r0 * ENC_HP_LD + k0 + rr];
                af[mt][1] = Hpu[(r0 + 8) * ENC_HP_LD + k0 + rr];
                af[mt][2] = Hpu[r0 * ENC_HP_LD + k0 + rr + 4];
                af[mt][3] = Hpu[(r0 + 8) * ENC_HP_LD + k0 + rr + 4];
            }
            unsigned bf[4][2];
            #pragma unroll
            for (int nt = 0; nt < 4; ++nt) {
                int n = wn * 32 + nt * 8 + qp;
                bf[nt][0] = sWu[(k0 + rr) * ENC_SW_LD + n];
                bf[nt][1] = sWu[(k0 + 4 + rr) * ENC_SW_LD + n];
            }
            #pragma unroll
            for (int mt = 0; mt < 2; ++mt)
                #pragma unroll
                for (int nt = 0; nt < 4; ++nt)
                    mma_tf32(acc[mt][nt], af[mt], bf[nt]);
        }

        #pragma unroll
        for (int nt = 0; nt < 4; ++nt) {
            int n = wn * 32 + nt * 8 + 2 * rr;
            float bv0 = b3[nc * 128 + n];
            float bv1 = b3[nc * 128 + n + 1];
            float m0 = 0.f, m1 = 0.f;
            #pragma unroll
            for (int mt = 0; mt < 2; ++mt) {
                float* d = acc[mt][nt];
                m0 = fmaxf(m0, fmaxf(d[0] + bv0, d[2] + bv0));
                m1 = fmaxf(m1, fmaxf(d[1] + bv1, d[3] + bv1));
            }
            #pragma unroll
            for (int s = 4; s < 32; s <<= 1) {
                m0 = fmaxf(m0, __shfl_xor_sync(0xffffffffu, m0, s));
                m1 = fmaxf(m1, __shfl_xor_sync(0xffffffffu, m1, s));
            }
            if (qp == 0) {
                sRed[wm * 128 + n]     = m0;
                sRed[wm * 128 + n + 1] = m1;
            }
        }
        __syncthreads();
        if (tid < 128) {
            float m = fmaxf(fmaxf(sRed[tid], sRed[128 + tid]),
                            fmaxf(sRed[256 + tid], sRed[384 + tid]));
            atomicMax((int*)&g_feat[b * 512 + nc * 128 + tid], __float_as_int(m));
        }
        __syncthreads();
    }
}

// ---------------------------------------------------------------------------
// Head MLP: 512 -> 256 -> 128 -> 256 (writes g_h directly)
// ---------------------------------------------------------------------------
__global__ void __launch_bounds__(512) head_kernel(
    const float* __restrict__ w1, const float* __restrict__ b1,
    const float* __restrict__ w2, const float* __restrict__ b2,
    const float* __restrict__ w3, const float* __restrict__ b3)
{
    __shared__ float sh[512];
    __shared__ float pp[512];
    __shared__ float s1[256];
    __shared__ float s2[128];
    int b = blockIdx.x, tid = threadIdx.x;
    sh[tid] = g_feat[b * 512 + tid];
    __syncthreads();
    {
        int j = tid & 255, half = tid >> 8, k0 = half * 256;
        const float* wp = w1 + (size_t)k0 * 256 + j;
        float a0 = 0, a1 = 0, a2 = 0, a3 = 0;
        #pragma unroll 8
        for (int k = 0; k < 256; k += 4) {
            a0 += sh[k0 + k]     * wp[(size_t)k * 256];
            a1 += sh[k0 + k + 1] * wp[(size_t)(k + 1) * 256];
            a2 += sh[k0 + k + 2] * wp[(size_t)(k + 2) * 256];
            a3 += sh[k0 + k + 3] * wp[(size_t)(k + 3) * 256];
        }
        pp[tid] = (a0 + a1) + (a2 + a3);
    }
    __syncthreads();
    if (tid < 256) s1[tid] = fmaxf(b1[tid] + pp[tid] + pp[tid + 256], 0.f);
    __syncthreads();
    {
        int j = tid & 127, q = tid >> 7, k0 = q * 64;
        const float* wp = w2 + k0 * 128 + j;
        float a0 = 0, a1 = 0;
        #pragma unroll 8
        for (int k = 0; k < 64; k += 2) {
            a0 += s1[k0 + k]     * wp[k * 128];
            a1 += s1[k0 + k + 1] * wp[(k + 1) * 128];
        }
        pp[tid] = a0 + a1;
    }
    __syncthreads();
    if (tid < 128) s2[tid] = fmaxf(b2[tid] + pp[tid] + pp[tid + 128] + pp[tid + 256] + pp[tid + 384], 0.f);
    __syncthreads();
    {
        int j = tid & 255, half = tid >> 8, k0 = half * 64;
        const float* wp = w3 + k0 * 256 + j;
        float a0 = 0, a1 = 0;
        #pragma unroll 8
        for (int k = 0; k < 64; k += 2) {
            a0 += s2[k0 + k]     * wp[k * 256];
            a1 += s2[k0 + k + 1] * wp[(k + 1) * 256];
        }
        pp[tid] = a0 + a1;
    }
    __syncthreads();
    if (tid < 256) g_h[b * HID + tid] = b3[tid] + pp[tid] + pp[tid + 256];
}

// ---------------------------------------------------------------------------
// GRU rollout v4: 128 blocks x 128 threads, grid-synced weight-stationary GEMM
//  - block = GEMM tile (32 batch x 48 cols), W-tile in smem staged ONCE
//  - gates + out-MLP for batches {2*bid, 2*bid+1} local to the block
//  - 2 flag barriers/step; barrier-B arrival signaled before out-MLP
// ---------------------------------------------------------------------------
#define GRU_SMEM_FLOATS 40728

__global__ void __launch_bounds__(128) gru_kernel(
    const float* __restrict__ Wih, const float* __restrict__ bih, const float* __restrict__ bhh,
    const float* __restrict__ ow1, const float* __restrict__ ob1,
    const float* __restrict__ ow2, const float* __restrict__ ob2,
    const float* __restrict__ ow3, const float* __restrict__ ob3,
    const int* __restrict__ horizon_p, float* __restrict__ out, int out_size)
{
    extern __shared__ float sm[];
    float* s_W   = sm;                 // 12288: W tile [k][48]
    float* s_hd  = s_W + 12288;        // 16896: h dup [k][33 float2] (pad)
    float* s_Wih = s_hd + 16896;       // 4608
    float* s_bih = s_Wih + 4608;       // 768
    float* s_bhh = s_bih + 768;        // 768
    float* s_w2  = s_bhh + 768;        // 4096
    float* s_w3  = s_w2 + 4096;        // 384
    float* s_b1  = s_w3 + 384;         // 64
    float* s_b2  = s_b1 + 64;          // 64
    float* s_b3  = s_b2 + 64;          // 8
    float* s_hn  = s_b3 + 8;           // 512 (2 rows x 256)
    float* s_x   = s_hn + 512;         // 16
    float* s_o1  = s_x + 16;           // 128
    float* s_o2  = s_o1 + 128;         // 128

    const int tid = threadIdx.x;
    const int bid = blockIdx.x;
    const int m0  = (bid >> 4) * 32;   // batch-tile origin
    const int n0  = (bid & 15) * 48;   // col-tile origin
    const int gb0 = bid * 2;           // gate/MLP batches: gb0, gb0+1

    // ---- one-time staging ----
    for (int idx = tid; idx < 12288; idx += 128) {
        int k = idx / 48, j = idx - k * 48;
        s_W[idx] = g_WhhT[(size_t)k * 768 + n0 + j];
    }
    for (int i = tid; i < 4608; i += 128) s_Wih[i] = Wih[i];
    for (int i = tid; i < 768;  i += 128) { s_bih[i] = bih[i]; s_bhh[i] = bhh[i]; }
    for (int i = tid; i < 4096; i += 128) s_w2[i] = ow2[i];
    for (int i = tid; i < 384;  i += 128) s_w3[i] = ow3[i];
    if (tid < 64) { s_b1[tid] = ob1[tid]; s_b2[tid] = ob2[tid]; }
    if (tid < 6)  s_b3[tid] = ob3[tid];
    if (tid < 16) s_x[tid] = 0.f;
    __syncthreads();

    int T = 50;
    if (horizon_p) {
        int v = *horizon_p;
        if (v > 0 && v <= 1000000) T = v;
        else {
            float fv = __int_as_float(v);
            if (fv > 0.f && fv <= 1000000.f) T = (int)fv;
        }
    }
    const int off2 = out_size >> 1;

    const int tx = tid & 7;            // 8 col-groups x 6 cols
    const int ty = tid >> 3;           // 16 row-groups x 2 rows
    float2* hd2 = (float2*)s_hd;

    for (int t = 0; t < T; ++t) {
        // ---- stage h tile (32 rows) duplicated ----
        for (int idx = tid; idx < 2048; idx += 128) {
            int r = idx >> 6, kq = idx & 63;
            float4 v = *(const float4*)&g_h[(m0 + r) * 256 + kq * 4];
            hd2[(kq*4+0)*33 + r] = make_float2(v.x, v.x);
            hd2[(kq*4+1)*33 + r] = make_float2(v.y, v.y);
            hd2[(kq*4+2)*33 + r] = make_float2(v.z, v.z);
            hd2[(kq*4+3)*33 + r] = make_float2(v.w, v.w);
        }
        __syncthreads();

        // ---- GEMM tile: 2 rows x 6 cols per thread, packed f32x2 ----
        ull a00 = 0, a01 = 0, a02 = 0, a10 = 0, a11 = 0, a12 = 0;
        {
            const ull* Wp = (const ull*)(s_W) + tx * 3;
            const ull* Hp = (const ull*)(s_hd) + ty * 2;
            #pragma unroll 4
            for (int k = 0; k < 256; ++k) {
                ull w0 = Wp[0], w1 = Wp[1], w2v = Wp[2];
                ull h0 = Hp[0], h1 = Hp[1];
                FMA2(a00, w0, h0); FMA2(a01, w1, h0); FMA2(a02, w2v, h0);
                FMA2(a10, w0, h1); FMA2(a11, w1, h1); FMA2(a12, w2v, h1);
                Wp += 24; Hp += 33;
            }
        }
        {
            int row0 = m0 + ty * 2;
            int col0 = n0 + tx * 6;
            ull* d0 = (ull*)&g_gh[(size_t)row0 * 768 + col0];
            ull* d1 = (ull*)&g_gh[(size_t)(row0 + 1) * 768 + col0];
            d0[0] = a00; d0[1] = a01; d0[2] = a02;
            d1[0] = a10; d1[1] = a11; d1[2] = a12;
        }

        // ---- barrier A: all gh tiles written ----
        __threadfence();
        __syncthreads();
        if (tid == 0) atomicExch(&g_barA[bid], t + 1);
        while (((volatile int*)g_barA)[tid] < t + 1) {}
        __threadfence();
        __syncthreads();

        // ---- gates for batches gb0, gb0+1 (512 items) ----
        #pragma unroll
        for (int it = 0; it < 4; ++it) {
            int item = tid + it * 128;
            int r = item >> 8, kk = item & 255;
            int gb = gb0 + r;
            float x0 = s_x[r*8+0], x1 = s_x[r*8+1], x2 = s_x[r*8+2];
            float x3 = s_x[r*8+3], x4 = s_x[r*8+4], x5 = s_x[r*8+5];
            const float* wr = s_Wih + kk * 6;
            const float* wz = s_Wih + (256 + kk) * 6;
            const float* wn = s_Wih + (512 + kk) * 6;
            float gir = s_bih[kk]       + x0*wr[0]+x1*wr[1]+x2*wr[2]+x3*wr[3]+x4*wr[4]+x5*wr[5];
            float giz = s_bih[256 + kk] + x0*wz[0]+x1*wz[1]+x2*wz[2]+x3*wz[3]+x4*wz[4]+x5*wz[5];
            float gin = s_bih[512 + kk] + x0*wn[0]+x1*wn[1]+x2*wn[2]+x3*wn[3]+x4*wn[4]+x5*wn[5];
            float ghr = __ldcg(&g_gh[(size_t)gb * 768 + kk]);
            float ghz = __ldcg(&g_gh[(size_t)gb * 768 + 256 + kk]);
            float ghn = __ldcg(&g_gh[(size_t)gb * 768 + 512 + kk]);
            float rr = sigf(gir + ghr + s_bhh[kk]);
            float zz = sigf(giz + ghz + s_bhh[256 + kk]);
            float nn = tanhfast(gin + rr * (ghn + s_bhh[512 + kk]));
            float hp = g_h[gb * 256 + kk];
            float hn = (1.f - zz) * nn + zz * hp;
            g_h[gb * 256 + kk] = hn;
            s_hn[r * 256 + kk] = hn;
        }

        // ---- barrier B arrival (h fully written) — then overlap out-MLP ----
        __threadfence();
        __syncthreads();
        if (tid == 0) atomicExch(&g_barB[bid], t + 1);

        // ---- out MLP: 2 rows, 256 -> 64 -> 64 -> 6 ----
        {
            int r = tid >> 6, j = tid & 63;
            const float* hb = s_hn + r * 256;
            const float* wp = ow1 + j;
            float a0 = 0, a1 = 0, a2 = 0, a3 = 0;
            #pragma unroll 8
            for (int k = 0; k < 256; k += 4) {
                a0 += hb[k]     * wp[k * 64];
                a1 += hb[k + 1] * wp[(k + 1) * 64];
                a2 += hb[k + 2] * wp[(k + 2) * 64];
                a3 += hb[k + 3] * wp[(k + 3) * 64];
            }
            s_o1[tid] = fmaxf(s_b1[j] + (a0 + a1) + (a2 + a3), 0.f);
        }
        __syncthreads();
        {
            int r = tid >> 6, j = tid & 63;
            float a0 = 0, a1 = 0;
            #pragma unroll 8
            for (int k = 0; k < 64; k += 2) {
                a0 += s_o1[r*64 + k]     * s_w2[k * 64 + j];
                a1 += s_o1[r*64 + k + 1] * s_w2[(k + 1) * 64 + j];
            }
            s_o2[tid] = fmaxf(s_b2[j] + a0 + a1, 0.f);
        }
        __syncthreads();
        if (tid < 12) {
            int r = tid / 6, aa = tid % 6;
            float d0 = 0, d1 = 0;
            #pragma unroll 8
            for (int k = 0; k < 64; k += 2) {
                d0 += s_o2[r*64 + k]     * s_w3[k * 6 + aa];
                d1 += s_o2[r*64 + k + 1] * s_w3[(k + 1) * 6 + aa];
            }
            float d = s_b3[aa] + d0 + d1;
            float xn = s_x[r*8 + aa] + d;
            s_x[r*8 + aa] = xn;
            int b = gb0 + r;
            size_t o = ((size_t)b * T + t) * 6 + aa;
            out[o] = d;
            out[off2 + o] = xn;
        }

        // ---- barrier B completion: h consistent for next GEMM ----
        while (((volatile int*)g_barB)[tid] < t + 1) {}
        __threadfence();
        __syncthreads();
    }
}

// ---------------------------------------------------------------------------
// launch
// ---------------------------------------------------------------------------
extern "C" void kernel_launch(void* const* d_in, const int* in_sizes, int n_in,
                              void* d_out, int out_size)
{
    int hpos = -1;
    for (int i = 0; i < n_in; ++i) if (in_sizes[i] == 1) hpos = i;

    const float* ins[23];
    int j = 0;
    for (int i = 0; i < n_in && j < 23; ++i) {
        if (i == hpos) continue;
        ins[j++] = (const float*)d_in[i];
    }
    const int* hp = (hpos >= 0) ? (const int*)d_in[hpos] : nullptr;

    // ins: 0 data | 1 enc_w1 2 enc_b1 3 enc_w2 4 enc_b2 5 enc_w3 6 enc_b3
    //      7 mlp_w1 8 mlp_b1 9 mlp_w2 10 mlp_b2 11 mlp_w3 12 mlp_b3
    //      13 W_ih 14 W_hh 15 b_ih 16 b_hh
    //      17 out_w1 18 out_b1 19 out_w2 20 out_b2 21 out_w3 22 out_b3

    const int enc_smem = ENC_SMEM_FLOATS * 4;
    const int gru_smem = GRU_SMEM_FLOATS * 4;
    cudaFuncSetAttribute(enc_kernel, cudaFuncAttributeMaxDynamicSharedMemorySize, enc_smem);
    cudaFuncSetAttribute(gru_kernel, cudaFuncAttributeMaxDynamicSharedMemorySize, gru_smem);

    zero_feat_kernel<<<512, 256>>>();
    transpose_whh_kernel<<<768, 256>>>(ins[14]);
    prep_w3_kernel<<<256, 256>>>(ins[5]);
    zero_flags_kernel<<<1, 128>>>();
    enc_kernel<<<dim3(8, 256), 512, enc_smem>>>(ins[0], ins[1], ins[2], ins[3], ins[4], ins[6]);
    head_kernel<<<256, 512>>>(ins[7], ins[8], ins[9], ins[10], ins[11], ins[12]);
    gru_kernel<<<GRU_BLOCKS, 128, gru_smem>>>(ins[13], ins[15], ins[16],
                                              ins[17], ins[18], ins[19], ins[20], ins[21], ins[22],
                                              hp, (float*)d_out, out_size);
}

// round 9
// speedup vs baseline: 1.9605x; 1.9605x over previous
#include <cuda_runtime.h>
#include <cuda_bf16.h>
#include <cstdint>
#include <cstddef>

// ---------------------------------------------------------------------------
// Problem constants
// ---------------------------------------------------------------------------
#define BATCH   256
#define NPTS    1024
#define HID     256
#define ACT     6
#define GRU_BLOCKS 128

// device scratch
__device__ float g_feat[BATCH * 512];
__device__ float g_gruh[BATCH * HID];
__device__ float g_WhhT[HID * 768];
__device__ unsigned g_W3tf[4 * 128 * 128];   // tf32 image, [nc][k][n]
__device__ unsigned g_W2tf[64 * 128];        // tf32 image of W2 [k][j]
// GRU pair-exchange payload: [parity][block][4*384 gh + 16 x] + flags
__device__ float g_pay[2][GRU_BLOCKS][1552];
__device__ int   g_flag[GRU_BLOCKS];

// ---------------------------------------------------------------------------
// helpers
// ---------------------------------------------------------------------------
__device__ __forceinline__ unsigned f2tf(float x) {
    unsigned u; asm("cvt.rna.tf32.f32 %0, %1;" : "=r"(u) : "f"(x)); return u;
}

__device__ __forceinline__ void mma_tf32(float* d, const unsigned* a, const unsigned* b) {
    asm volatile(
        "mma.sync.aligned.m16n8k8.row.col.f32.tf32.tf32.f32 "
        "{%0,%1,%2,%3}, {%4,%5,%6,%7}, {%8,%9}, {%0,%1,%2,%3};\n"
        : "+f"(d[0]), "+f"(d[1]), "+f"(d[2]), "+f"(d[3])
        : "r"(a[0]), "r"(a[1]), "r"(a[2]), "r"(a[3]), "r"(b[0]), "r"(b[1]));
}

__device__ __forceinline__ float sigf(float x) { return 1.f / (1.f + __expf(-x)); }
__device__ __forceinline__ float tanhfast(float x) { return 2.f / (1.f + __expf(-2.f * x)) - 1.f; }

// ---------------------------------------------------------------------------
// fused prep kernel: zero_feat | Whh transpose | W3 tf32 | W2 tf32 | flags
// ---------------------------------------------------------------------------
__global__ void prep_kernel(const float* __restrict__ Whh,
                            const float* __restrict__ w3,
                            const float* __restrict__ w2) {
    int idx = blockIdx.x * 256 + threadIdx.x;
    if (idx < 131072) { g_feat[idx] = 0.f; return; }
    idx -= 131072;
    if (idx < 196608) {
        int k = idx / 768, j = idx - k * 768;
        g_WhhT[idx] = Whh[j * 256 + k];
        return;
    }
    idx -= 196608;
    if (idx < 65536) {
        int nc = idx >> 14, r = idx & 16383;
        int k = r >> 7, n = r & 127;
        g_W3tf[idx] = f2tf(w3[(size_t)k * 512 + nc * 128 + n]);
        return;
    }
    idx -= 65536;
    if (idx < 8192) { g_W2tf[idx] = f2tf(w2[idx]); return; }
    idx -= 8192;
    if (idx < GRU_BLOCKS) g_flag[idx] = 0;
}

// ---------------------------------------------------------------------------
// Fused PointNet encoder: 3->64 (fp32 SIMT) -> 128 (tf32 mma) -> 512 (tf32 mma)
// grid (8 chunks, 256 batches), 512 threads (16 warps), 128 points/block
// ---------------------------------------------------------------------------
#define ENC_HP_LD 132
#define ENC_SW_LD 136
#define ENC_A2_LD 68
#define ENC_SMEM_FLOATS (16896 + 17920)

__global__ void __launch_bounds__(512) enc_kernel(
    const float* __restrict__ data,
    const float* __restrict__ w1, const float* __restrict__ b1,
    const float* __restrict__ b2, const float* __restrict__ b3)
{
    extern __shared__ float sm[];
    float* Hp   = sm;                 // [128 pts][128 k] tf32 bits, LD=132
    float* work = sm + 16896;
    float* sW   = work;               // layer3: W3 chunk [128][136] tf32
    float* sRed = work + 17408;       // 4x128
    __shared__ float sPts[128 * 3];

    const int tid   = threadIdx.x;
    const int b     = blockIdx.y;
    const int chunk = blockIdx.x;

    unsigned* A2 = (unsigned*)work;            // layer-1 out [i][68] tf32
    unsigned* B2 = (unsigned*)(work + 8704);   // W2 [k][136] tf32

    // ---- stage points + W2 (tf32 image) ----
    const float* dptr = data + (size_t)(b * NPTS + chunk * 128) * 3;
    if (tid < 384) sPts[tid] = dptr[tid];
    for (int idx = tid; idx < 8192; idx += 512) {
        int k = idx >> 7, j = idx & 127;
        B2[k * ENC_SW_LD + j] = g_W2tf[idx];
    }
    __syncthreads();

    // ---- layer 1: A2[i][k] = tf32(relu(p . w1col + b1)) ----
    #pragma unroll
    for (int it = 0; it < 16; ++it) {
        int idx = tid + it * 512;
        int k = idx >> 7, i = idx & 127;
        float v = b1[k] + sPts[i*3] * w1[k] + sPts[i*3+1] * w1[64 + k] + sPts[i*3+2] * w1[128 + k];
        A2[i * ENC_A2_LD + k] = f2tf(fmaxf(v, 0.f));
    }
    __syncthreads();

    const int lane = tid & 31, wrp = tid >> 5;
    const int wm = wrp & 3, wn = wrp >> 2;
    const int qp = lane >> 2, rr = lane & 3;
    unsigned* Hpu = (unsigned*)Hp;

    // ---- layer 2 via tf32 mma: M=128, N=128, K=64 -> Hp tf32 ----
    {
        float acc[2][4][4];
        #pragma unroll
        for (int mt = 0; mt < 2; ++mt)
            #pragma unroll
            for (int nt = 0; nt < 4; ++nt)
                #pragma unroll
                for (int q = 0; q < 4; ++q) acc[mt][nt][q] = 0.f;

        #pragma unroll 2
        for (int ks = 0; ks < 8; ++ks) {
            int k0 = ks * 8;
            unsigned af[2][4];
            #pragma unroll
            for (int mt = 0; mt < 2; ++mt) {
                int r0 = wm * 32 + mt * 16 + qp;
                af[mt][0] = A2[r0 * ENC_A2_LD + k0 + rr];
                af[mt][1] = A2[(r0 + 8) * ENC_A2_LD + k0 + rr];
                af[mt][2] = A2[r0 * ENC_A2_LD + k0 + rr + 4];
                af[mt][3] = A2[(r0 + 8) * ENC_A2_LD + k0 + rr + 4];
            }
            unsigned bf[4][2];
            #pragma unroll
            for (int nt = 0; nt < 4; ++nt) {
                int n = wn * 32 + nt * 8 + qp;
                bf[nt][0] = B2[(k0 + rr) * ENC_SW_LD + n];
                bf[nt][1] = B2[(k0 + 4 + rr) * ENC_SW_LD + n];
            }
            #pragma unroll
            for (int mt = 0; mt < 2; ++mt)
                #pragma unroll
                for (int nt = 0; nt < 4; ++nt)
                    mma_tf32(acc[mt][nt], af[mt], bf[nt]);
        }

        // epilogue: bias + relu + tf32 -> Hp[i][k]
        #pragma unroll
        for (int mt = 0; mt < 2; ++mt) {
            int r0 = wm * 32 + mt * 16 + qp;
            #pragma unroll
            for (int nt = 0; nt < 4; ++nt) {
                int c0 = wn * 32 + nt * 8 + 2 * rr;
                float bv0 = b2[c0], bv1 = b2[c0 + 1];
                float* d = acc[mt][nt];
                unsigned u0 = f2tf(fmaxf(d[0] + bv0, 0.f));
                unsigned u1 = f2tf(fmaxf(d[1] + bv1, 0.f));
                unsigned u2 = f2tf(fmaxf(d[2] + bv0, 0.f));
                unsigned u3 = f2tf(fmaxf(d[3] + bv1, 0.f));
                *(uint2*)(Hpu + r0 * ENC_HP_LD + c0)       = make_uint2(u0, u1);
                *(uint2*)(Hpu + (r0 + 8) * ENC_HP_LD + c0) = make_uint2(u2, u3);
            }
        }
    }
    __syncthreads();

    // ---- layer 3: tf32 mma, 4 N-chunks of 128 ----
    unsigned* sWu = (unsigned*)sW;

    for (int nc = 0; nc < 4; ++nc) {
        {
            const float* src = (const float*)(g_W3tf + nc * 16384);
            for (int i = tid * 4; i < 16384; i += 2048) {
                int k = i >> 7, n = i & 127;
                *(float4*)(sW + k * ENC_SW_LD + n) = *(const float4*)(src + i);
            }
        }
        __syncthreads();

        float acc[2][4][4];
        #pragma unroll
        for (int mt = 0; mt < 2; ++mt)
            #pragma unroll
            for (int nt = 0; nt < 4; ++nt)
                #pragma unroll
                for (int q = 0; q < 4; ++q) acc[mt][nt][q] = 0.f;

        #pragma unroll 2
        for (int ks = 0; ks < 16; ++ks) {
            int k0 = ks * 8;
            unsigned af[2][4];
            #pragma unroll
            for (int mt = 0; mt < 2; ++mt) {
                int r0 = wm * 32 + mt * 16 + qp;
                af[mt][0] = Hpu[r0 * ENC_HP_LD + k0 + rr];
                af[mt][1] = Hpu[(r0 + 8) * ENC_HP_LD + k0 + rr];
                af[mt][2] = Hpu[r0 * ENC_HP_LD + k0 + rr + 4];
                af[mt][3] = Hpu[(r0 + 8) * ENC_HP_LD + k0 + rr + 4];
            }
            unsigned bf[4][2];
            #pragma unroll
            for (int nt = 0; nt < 4; ++nt) {
                int n = wn * 32 + nt * 8 + qp;
                bf[nt][0] = sWu[(k0 + rr) * ENC_SW_LD + n];
                bf[nt][1] = sWu[(k0 + 4 + rr) * ENC_SW_LD + n];
            }
            #pragma unroll
            for (int mt = 0; mt < 2; ++mt)
                #pragma unroll
                for (int nt = 0; nt < 4; ++nt)
                    mma_tf32(acc[mt][nt], af[mt], bf[nt]);
        }

        #pragma unroll
        for (int nt = 0; nt < 4; ++nt) {
            int n = wn * 32 + nt * 8 + 2 * rr;
            float bv0 = b3[nc * 128 + n];
            float bv1 = b3[nc * 128 + n + 1];
            float m0 = 0.f, m1 = 0.f;
            #pragma unroll
            for (int mt = 0; mt < 2; ++mt) {
                float* d = acc[mt][nt];
                m0 = fmaxf(m0, fmaxf(d[0] + bv0, d[2] + bv0));
                m1 = fmaxf(m1, fmaxf(d[1] + bv1, d[3] + bv1));
            }
            #pragma unroll
            for (int s = 4; s < 32; s <<= 1) {
                m0 = fmaxf(m0, __shfl_xor_sync(0xffffffffu, m0, s));
                m1 = fmaxf(m1, __shfl_xor_sync(0xffffffffu, m1, s));
            }
            if (qp == 0) {
                sRed[wm * 128 + n]     = m0;
                sRed[wm * 128 + n + 1] = m1;
            }
        }
        __syncthreads();
        if (tid < 128) {
            float m = fmaxf(fmaxf(sRed[tid], sRed[128 + tid]),
                            fmaxf(sRed[256 + tid], sRed[384 + tid]));
            atomicMax((int*)&g_feat[b * 512 + nc * 128 + tid], __float_as_int(m));
        }
        __syncthreads();
    }
}

// ---------------------------------------------------------------------------
// Head MLP: 512 -> 256 -> 128 -> 256, 512 threads, k-split + smem combine
// ---------------------------------------------------------------------------
__global__ void __launch_bounds__(512) head_kernel(
    const float* __restrict__ w1, const float* __restrict__ b1,
    const float* __restrict__ w2, const float* __restrict__ b2,
    const float* __restrict__ w3, const float* __restrict__ b3)
{
    __shared__ float sh[512];
    __shared__ float pp[512];
    __shared__ float s1[256];
    __shared__ float s2[128];
    int b = blockIdx.x, tid = threadIdx.x;
    sh[tid] = g_feat[b * 512 + tid];
    __syncthreads();
    {
        int j = tid & 255, half = tid >> 8, k0 = half * 256;
        const float* wp = w1 + (size_t)k0 * 256 + j;
        float a0 = 0, a1 = 0, a2 = 0, a3 = 0;
        #pragma unroll 8
        for (int k = 0; k < 256; k += 4) {
            a0 += sh[k0 + k]     * wp[(size_t)k * 256];
            a1 += sh[k0 + k + 1] * wp[(size_t)(k + 1) * 256];
            a2 += sh[k0 + k + 2] * wp[(size_t)(k + 2) * 256];
            a3 += sh[k0 + k + 3] * wp[(size_t)(k + 3) * 256];
        }
        pp[tid] = (a0 + a1) + (a2 + a3);
    }
    __syncthreads();
    if (tid < 256) s1[tid] = fmaxf(b1[tid] + pp[tid] + pp[tid + 256], 0.f);
    __syncthreads();
    {
        int j = tid & 127, q = tid >> 7, k0 = q * 64;
        const float* wp = w2 + k0 * 128 + j;
        float a0 = 0, a1 = 0;
        #pragma unroll 8
        for (int k = 0; k < 64; k += 2) {
            a0 += s1[k0 + k]     * wp[k * 128];
            a1 += s1[k0 + k + 1] * wp[(k + 1) * 128];
        }
        pp[tid] = a0 + a1;
    }
    __syncthreads();
    if (tid < 128) s2[tid] = fmaxf(b2[tid] + pp[tid] + pp[tid + 128] + pp[tid + 256] + pp[tid + 384], 0.f);
    __syncthreads();
    {
        int j = tid & 255, half = tid >> 8, k0 = half * 64;
        const float* wp = w3 + k0 * 256 + j;
        float a0 = 0, a1 = 0;
        #pragma unroll 8
        for (int k = 0; k < 64; k += 2) {
            a0 += s2[k0 + k]     * wp[k * 256];
            a1 += s2[k0 + k + 1] * wp[(k + 1) * 256];
        }
        pp[tid] = a0 + a1;
    }
    __syncthreads();
    if (tid < 256) g_gruh[b * HID + tid] = b3[tid] + pp[tid] + pp[tid + 256];
}

// ---------------------------------------------------------------------------
// GRU rollout v3 (R7 passing version, verbatim): 128 blocks = 64 pairs
// ---------------------------------------------------------------------------
#define GRU_SMEM_FLOATS 36392

__global__ void __launch_bounds__(384) gru_kernel(
    const float* __restrict__ Wih, const float* __restrict__ bih, const float* __restrict__ bhh,
    const float* __restrict__ ow1, const float* __restrict__ ob1,
    const float* __restrict__ ow2, const float* __restrict__ ob2,
    const float* __restrict__ ow3, const float* __restrict__ ob3,
    const int* __restrict__ horizon_p, float* __restrict__ out, int out_size)
{
    extern __shared__ float sm[];
    float* s_Wih  = sm;
    float* s_bih  = s_Wih + 4608;
    float* s_bhh  = s_bih + 768;
    float* s_w1   = s_bhh + 768;
    float* s_w2   = s_w1 + 16384;
    float* s_w3   = s_w2 + 4096;
    float* s_b1   = s_w3 + 384;
    float* s_b2   = s_b1 + 64;
    float* s_b3   = s_b2 + 64;
    float* s_h    = s_b3 + 8;
    float* s_x    = s_h + 1024;
    float* s_gh   = s_x + 32;
    float* s_part = s_gh + 3072;
    float* s_p1   = s_part + 4608;
    float* s_o1   = s_p1 + 256;
    float* s_o2   = s_o1 + 128;

    const int tid     = threadIdx.x;
    const int bid     = blockIdx.x;
    const int pairid  = bid >> 1;
    const int half    = bid & 1;
    const int partner = bid ^ 1;
    const int b0      = pairid * 4;

    for (int i = tid; i < 4608;  i += 384) s_Wih[i] = Wih[i];
    for (int i = tid; i < 768;   i += 384) { s_bih[i] = bih[i]; s_bhh[i] = bhh[i]; }
    for (int i = tid; i < 16384; i += 384) s_w1[i] = ow1[i];
    for (int i = tid; i < 4096;  i += 384) s_w2[i] = ow2[i];
    if (tid < 384) s_w3[tid] = ow3[tid];
    if (tid < 64) { s_b1[tid] = ob1[tid]; s_b2[tid] = ob2[tid]; }
    if (tid < 6)  s_b3[tid] = ob3[tid];
    for (int i = tid; i < 1024; i += 384) {
        int r = i >> 8, k = i & 255;
        s_h[i] = g_gruh[(b0 + r) * HID + k];
    }
    if (tid < 32) s_x[tid] = 0.f;
    __syncthreads();

    int T = 50;
    if (horizon_p) {
        int v = *horizon_p;
        if (v > 0 && v <= 1000000) T = v;
        else {
            float fv = __int_as_float(v);
            if (fv > 0.f && fv <= 1000000.f) T = (int)fv;
        }
    }
    const int off2 = out_size >> 1;

    const int jg   = tid % 96;
    const int ks   = tid / 96;
    const int k0   = ks * 64;
    const int jcol = half * 384 + jg * 4;
    const float* Wcol = g_WhhT + jcol;

    for (int t = 0; t < T; ++t) {
        const int par = t & 1;
        float* pay_out = &g_pay[par][bid][0];
        const float* pay_in = &g_pay[par][partner][0];

        float acc[4][4];
        #pragma unroll
        for (int r = 0; r < 4; ++r)
            #pragma unroll
            for (int c = 0; c < 4; ++c) acc[r][c] = 0.f;

        #pragma unroll 2
        for (int kk = 0; kk < 64; kk += 4) {
            float4 h0 = *(float4*)&s_h[0 * 256 + k0 + kk];
            float4 h1 = *(float4*)&s_h[1 * 256 + k0 + kk];
            float4 h2 = *(float4*)&s_h[2 * 256 + k0 + kk];
            float4 h3 = *(float4*)&s_h[3 * 256 + k0 + kk];
            const float* wb = Wcol + (size_t)(k0 + kk) * 768;
            #pragma unroll
            for (int q = 0; q < 4; ++q) {
                float4 w = *(const float4*)(wb + (size_t)q * 768);
                float a0 = (q == 0) ? h0.x : (q == 1) ? h0.y : (q == 2) ? h0.z : h0.w;
                float a1 = (q == 0) ? h1.x : (q == 1) ? h1.y : (q == 2) ? h1.z : h1.w;
                float a2 = (q == 0) ? h2.x : (q == 1) ? h2.y : (q == 2) ? h2.z : h2.w;
                float a3 = (q == 0) ? h3.x : (q == 1) ? h3.y : (q == 2) ? h3.z : h3.w;
                acc[0][0] += a0*w.x; acc[0][1] += a0*w.y; acc[0][2] += a0*w.z; acc[0][3] += a0*w.w;
                acc[1][0] += a1*w.x; acc[1][1] += a1*w.y; acc[1][2] += a1*w.z; acc[1][3] += a1*w.w;
                acc[2][0] += a2*w.x; acc[2][1] += a2*w.y; acc[2][2] += a2*w.z; acc[2][3] += a2*w.w;
                acc[3][0] += a3*w.x; acc[3][1] += a3*w.y; acc[3][2] += a3*w.z; acc[3][3] += a3*w.w;
            }
        }

        if (ks > 0) {
            float* p = &s_part[((ks - 1) * 96 + jg) * 16];
            #pragma unroll
            for (int r = 0; r < 4; ++r)
                *(float4*)(p + r * 4) = make_float4(acc[r][0], acc[r][1], acc[r][2], acc[r][3]);
        }
        __syncthreads();
        if (ks == 0) {
            #pragma unroll
            for (int s = 0; s < 3; ++s) {
                const float* p = &s_part[(s * 96 + jg) * 16];
                #pragma unroll
                for (int r = 0; r < 4; ++r) {
                    float4 v = *(const float4*)(p + r * 4);
                    acc[r][0] += v.x; acc[r][1] += v.y; acc[r][2] += v.z; acc[r][3] += v.w;
                }
            }
            #pragma unroll
            for (int r = 0; r < 4; ++r) {
                float4 v = make_float4(acc[r][0], acc[r][1], acc[r][2], acc[r][3]);
                *(float4*)&s_gh[r * 768 + jcol] = v;
                *(float4*)&pay_out[r * 384 + jg * 4] = v;
            }
        }
        if (tid < 12) {
            int rl = tid / 6, a = tid % 6;
            pay_out[1536 + tid] = s_x[(half * 2 + rl) * 8 + a];
        }
        __threadfence();
        __syncthreads();
        if (tid == 0) {
            atomicExch(&g_flag[bid], t + 1);
            volatile int* f = &g_flag[partner];
            while (*f < t + 1) {}
            __threadfence();
        }
        __syncthreads();

        {
            int rr = tid / 96, off = (tid % 96) * 4;
            float4 v = __ldcg((const float4*)&pay_in[rr * 384 + off]);
            *(float4*)&s_gh[rr * 768 + (half ^ 1) * 384 + off] = v;
        }
        if (tid < 12) {
            int rl = tid / 6, a = tid % 6;
            s_x[((half ^ 1) * 2 + rl) * 8 + a] = __ldcg(&pay_in[1536 + tid]);
        }
        __syncthreads();

        #pragma unroll
        for (int it = 0; it < 3; ++it) {
            int item = tid + it * 384;
            if (item < 1024) {
                int r = item >> 8, kk = item & 255;
                float x0 = s_x[r*8+0], x1 = s_x[r*8+1], x2 = s_x[r*8+2];
                float x3 = s_x[r*8+3], x4 = s_x[r*8+4], x5 = s_x[r*8+5];
                const float* wr = s_Wih + kk * 6;
                const float* wz = s_Wih + (256 + kk) * 6;
                const float* wn = s_Wih + (512 + kk) * 6;
                float gir = s_bih[kk]       + x0*wr[0]+x1*wr[1]+x2*wr[2]+x3*wr[3]+x4*wr[4]+x5*wr[5];
                float giz = s_bih[256 + kk] + x0*wz[0]+x1*wz[1]+x2*wz[2]+x3*wz[3]+x4*wz[4]+x5*wz[5];
                float gin = s_bih[512 + kk] + x0*wn[0]+x1*wn[1]+x2*wn[2]+x3*wn[3]+x4*wn[4]+x5*wn[5];
                float rr = sigf(gir + s_gh[r*768 + kk] + s_bhh[kk]);
                float zz = sigf(giz + s_gh[r*768 + 256 + kk] + s_bhh[256 + kk]);
                float nn = tanhfast(gin + rr * (s_gh[r*768 + 512 + kk] + s_bhh[512 + kk]));
                s_h[r*256 + kk] = (1.f - zz) * nn + zz * s_h[r*256 + kk];
            }
        }
        __syncthreads();

        if (tid < 256) {
            int j = tid & 63, q = tid >> 6;
            int rl = q & 1, kh2 = q >> 1;
            const float* hb = s_h + (half * 2 + rl) * 256 + kh2 * 128;
            const float* wp = s_w1 + (kh2 * 128) * 64 + j;
            float a0 = 0, a1 = 0;
            #pragma unroll 8
            for (int k = 0; k < 128; k += 2) {
                a0 += hb[k]     * wp[k * 64];
                a1 += hb[k + 1] * wp[(k + 1) * 64];
            }
            s_p1[q * 64 + j] = a0 + a1;
        }
        __syncthreads();
        if (tid < 128) {
            int rl = tid >> 6, j = tid & 63;
            s_o1[tid] = fmaxf(s_b1[j] + s_p1[rl * 64 + j] + s_p1[(rl + 2) * 64 + j], 0.f);
        }
        __syncthreads();
        if (tid < 128) {
            int rl = tid >> 6, j = tid & 63;
            float a0 = 0, a1 = 0;
            #pragma unroll 8
            for (int k = 0; k < 64; k += 2) {
                a0 += s_o1[rl*64 + k]     * s_w2[k * 64 + j];
                a1 += s_o1[rl*64 + k + 1] * s_w2[(k + 1) * 64 + j];
            }
            s_o2[tid] = fmaxf(s_b2[j] + a0 + a1, 0.f);
        }
        __syncthreads();
        if (tid < 12) {
            int rl = tid / 6, a = tid % 6;
            float d0 = 0, d1 = 0;
            #pragma unroll 8
            for (int k = 0; k < 64; k += 2) {
                d0 += s_o2[rl*64 + k]     * s_w3[k * 6 + a];
                d1 += s_o2[rl*64 + k + 1] * s_w3[(k + 1) * 6 + a];
            }
            float d = s_b3[a] + d0 + d1;
            int rloc = half * 2 + rl;
            float xn = s_x[rloc * 8 + a] + d;
            s_x[rloc * 8 + a] = xn;
            int b = b0 + rloc;
            size_t o = ((size_t)b * T + t) * 6 + a;
            out[o] = d;
            out[off2 + o] = xn;
        }
        __syncthreads();
    }
}

// ---------------------------------------------------------------------------
// launch
// ---------------------------------------------------------------------------
extern "C" void kernel_launch(void* const* d_in, const int* in_sizes, int n_in,
                              void* d_out, int out_size)
{
    int hpos = -1;
    for (int i = 0; i < n_in; ++i) if (in_sizes[i] == 1) hpos = i;

    const float* ins[23];
    int j = 0;
    for (int i = 0; i < n_in && j < 23; ++i) {
        if (i == hpos) continue;
        ins[j++] = (const float*)d_in[i];
    }
    const int* hp = (hpos >= 0) ? (const int*)d_in[hpos] : nullptr;

    // ins: 0 data | 1 enc_w1 2 enc_b1 3 enc_w2 4 enc_b2 5 enc_w3 6 enc_b3
    //      7 mlp_w1 8 mlp_b1 9 mlp_w2 10 mlp_b2 11 mlp_w3 12 mlp_b3
    //      13 W_ih 14 W_hh 15 b_ih 16 b_hh
    //      17 out_w1 18 out_b1 19 out_w2 20 out_b2 21 out_w3 22 out_b3

    const int enc_smem = ENC_SMEM_FLOATS * 4;
    const int gru_smem = GRU_SMEM_FLOATS * 4;
    cudaFuncSetAttribute(enc_kernel, cudaFuncAttributeMaxDynamicSharedMemorySize, enc_smem);
    cudaFuncSetAttribute(gru_kernel, cudaFuncAttributeMaxDynamicSharedMemorySize, gru_smem);

    // prep tasks: 131072 feat + 196608 whhT + 65536 w3tf + 8192 w2tf + 128 flags
    prep_kernel<<<1569, 256>>>(ins[14], ins[5], ins[3]);
    enc_kernel<<<dim3(8, 256), 512, enc_smem>>>(ins[0], ins[1], ins[2], ins[4], ins[6]);
    head_kernel<<<256, 512>>>(ins[7], ins[8], ins[9], ins[10], ins[11], ins[12]);
    gru_kernel<<<GRU_BLOCKS, 384, gru_smem>>>(ins[13], ins[15], ins[16],
                                              ins[17], ins[18], ins[19], ins[20], ins[21], ins[22],
                                              hp, (float*)d_out, out_size);
}

// round 10
// speedup vs baseline: 2.0808x; 1.0614x over previous
#include <cuda_runtime.h>
#include <cuda_bf16.h>
#include <cstdint>
#include <cstddef>

// ---------------------------------------------------------------------------
// Problem constants
// ---------------------------------------------------------------------------
#define BATCH   256
#define NPTS    1024
#define HID     256
#define ACT     6
#define GRU_BLOCKS 128

// device scratch
__device__ float g_feat[BATCH * 512];
__device__ float g_gruh[BATCH * HID];
__device__ float g_WhhT[HID * 768];
__device__ unsigned g_W3tf[4 * 128 * 128];   // tf32 image, [nc][k][n]
__device__ unsigned g_W2tf[64 * 128];        // tf32 image of W2 [k][j]
// GRU pair-exchange payload: [parity][block][4*384 gh + 16 x] + flags
__device__ float g_pay[2][GRU_BLOCKS][1552];
__device__ int   g_flag[GRU_BLOCKS];

// ---------------------------------------------------------------------------
// helpers
// ---------------------------------------------------------------------------
__device__ __forceinline__ unsigned f2tf(float x) {
    unsigned u; asm("cvt.rna.tf32.f32 %0, %1;" : "=r"(u) : "f"(x)); return u;
}

__device__ __forceinline__ void mma_tf32(float* d, const unsigned* a, const unsigned* b) {
    asm volatile(
        "mma.sync.aligned.m16n8k8.row.col.f32.tf32.tf32.f32 "
        "{%0,%1,%2,%3}, {%4,%5,%6,%7}, {%8,%9}, {%0,%1,%2,%3};\n"
        : "+f"(d[0]), "+f"(d[1]), "+f"(d[2]), "+f"(d[3])
        : "r"(a[0]), "r"(a[1]), "r"(a[2]), "r"(a[3]), "r"(b[0]), "r"(b[1]));
}

__device__ __forceinline__ float sigf(float x) { return 1.f / (1.f + __expf(-x)); }
__device__ __forceinline__ float tanhfast(float x) { return 2.f / (1.f + __expf(-2.f * x)) - 1.f; }

// ---------------------------------------------------------------------------
// fused prep kernel: zero_feat | Whh transpose | W3 tf32 | W2 tf32 | flags
// ---------------------------------------------------------------------------
__global__ void prep_kernel(const float* __restrict__ Whh,
                            const float* __restrict__ w3,
                            const float* __restrict__ w2) {
    int idx = blockIdx.x * 256 + threadIdx.x;
    if (idx < 131072) { g_feat[idx] = 0.f; return; }
    idx -= 131072;
    if (idx < 196608) {
        int k = idx / 768, j = idx - k * 768;
        g_WhhT[idx] = Whh[j * 256 + k];
        return;
    }
    idx -= 196608;
    if (idx < 65536) {
        int nc = idx >> 14, r = idx & 16383;
        int k = r >> 7, n = r & 127;
        g_W3tf[idx] = f2tf(w3[(size_t)k * 512 + nc * 128 + n]);
        return;
    }
    idx -= 65536;
    if (idx < 8192) { g_W2tf[idx] = f2tf(w2[idx]); return; }
    idx -= 8192;
    if (idx < GRU_BLOCKS) g_flag[idx] = 0;
}

// ---------------------------------------------------------------------------
// Fused PointNet encoder: 3->64 (fp32 SIMT) -> 128 (tf32 mma) -> 512 (tf32 mma)
// grid (8 chunks, 256 batches), 512 threads (16 warps), 128 points/block
// (identical to R9 passing version)
// ---------------------------------------------------------------------------
#define ENC_HP_LD 132
#define ENC_SW_LD 136
#define ENC_A2_LD 68
#define ENC_SMEM_FLOATS (16896 + 17920)

__global__ void __launch_bounds__(512) enc_kernel(
    const float* __restrict__ data,
    const float* __restrict__ w1, const float* __restrict__ b1,
    const float* __restrict__ b2, const float* __restrict__ b3)
{
    extern __shared__ float sm[];
    float* Hp   = sm;
    float* work = sm + 16896;
    float* sW   = work;
    float* sRed = work + 17408;
    __shared__ float sPts[128 * 3];

    const int tid   = threadIdx.x;
    const int b     = blockIdx.y;
    const int chunk = blockIdx.x;

    unsigned* A2 = (unsigned*)work;
    unsigned* B2 = (unsigned*)(work + 8704);

    const float* dptr = data + (size_t)(b * NPTS + chunk * 128) * 3;
    if (tid < 384) sPts[tid] = dptr[tid];
    for (int idx = tid; idx < 8192; idx += 512) {
        int k = idx >> 7, j = idx & 127;
        B2[k * ENC_SW_LD + j] = g_W2tf[idx];
    }
    __syncthreads();

    #pragma unroll
    for (int it = 0; it < 16; ++it) {
        int idx = tid + it * 512;
        int k = idx >> 7, i = idx & 127;
        float v = b1[k] + sPts[i*3] * w1[k] + sPts[i*3+1] * w1[64 + k] + sPts[i*3+2] * w1[128 + k];
        A2[i * ENC_A2_LD + k] = f2tf(fmaxf(v, 0.f));
    }
    __syncthreads();

    const int lane = tid & 31, wrp = tid >> 5;
    const int wm = wrp & 3, wn = wrp >> 2;
    const int qp = lane >> 2, rr = lane & 3;
    unsigned* Hpu = (unsigned*)Hp;

    {
        float acc[2][4][4];
        #pragma unroll
        for (int mt = 0; mt < 2; ++mt)
            #pragma unroll
            for (int nt = 0; nt < 4; ++nt)
                #pragma unroll
                for (int q = 0; q < 4; ++q) acc[mt][nt][q] = 0.f;

        #pragma unroll 2
        for (int ks = 0; ks < 8; ++ks) {
            int k0 = ks * 8;
            unsigned af[2][4];
            #pragma unroll
            for (int mt = 0; mt < 2; ++mt) {
                int r0 = wm * 32 + mt * 16 + qp;
                af[mt][0] = A2[r0 * ENC_A2_LD + k0 + rr];
                af[mt][1] = A2[(r0 + 8) * ENC_A2_LD + k0 + rr];
                af[mt][2] = A2[r0 * ENC_A2_LD + k0 + rr + 4];
                af[mt][3] = A2[(r0 + 8) * ENC_A2_LD + k0 + rr + 4];
            }
            unsigned bf[4][2];
            #pragma unroll
            for (int nt = 0; nt < 4; ++nt) {
                int n = wn * 32 + nt * 8 + qp;
                bf[nt][0] = B2[(k0 + rr) * ENC_SW_LD + n];
                bf[nt][1] = B2[(k0 + 4 + rr) * ENC_SW_LD + n];
            }
            #pragma unroll
            for (int mt = 0; mt < 2; ++mt)
                #pragma unroll
                for (int nt = 0; nt < 4; ++nt)
                    mma_tf32(acc[mt][nt], af[mt], bf[nt]);
        }

        #pragma unroll
        for (int mt = 0; mt < 2; ++mt) {
            int r0 = wm * 32 + mt * 16 + qp;
            #pragma unroll
            for (int nt = 0; nt < 4; ++nt) {
                int c0 = wn * 32 + nt * 8 + 2 * rr;
                float bv0 = b2[c0], bv1 = b2[c0 + 1];
                float* d = acc[mt][nt];
                unsigned u0 = f2tf(fmaxf(d[0] + bv0, 0.f));
                unsigned u1 = f2tf(fmaxf(d[1] + bv1, 0.f));
                unsigned u2 = f2tf(fmaxf(d[2] + bv0, 0.f));
                unsigned u3 = f2tf(fmaxf(d[3] + bv1, 0.f));
                *(uint2*)(Hpu + r0 * ENC_HP_LD + c0)       = make_uint2(u0, u1);
                *(uint2*)(Hpu + (r0 + 8) * ENC_HP_LD + c0) = make_uint2(u2, u3);
            }
        }
    }
    __syncthreads();

    unsigned* sWu = (unsigned*)sW;

    for (int nc = 0; nc < 4; ++nc) {
        {
            const float* src = (const float*)(g_W3tf + nc * 16384);
            for (int i = tid * 4; i < 16384; i += 2048) {
                int k = i >> 7, n = i & 127;
                *(float4*)(sW + k * ENC_SW_LD + n) = *(const float4*)(src + i);
            }
        }
        __syncthreads();

        float acc[2][4][4];
        #pragma unroll
        for (int mt = 0; mt < 2; ++mt)
            #pragma unroll
            for (int nt = 0; nt < 4; ++nt)
                #pragma unroll
                for (int q = 0; q < 4; ++q) acc[mt][nt][q] = 0.f;

        #pragma unroll 2
        for (int ks = 0; ks < 16; ++ks) {
            int k0 = ks * 8;
            unsigned af[2][4];
            #pragma unroll
            for (int mt = 0; mt < 2; ++mt) {
                int r0 = wm * 32 + mt * 16 + qp;
                af[mt][0] = Hpu[r0 * ENC_HP_LD + k0 + rr];
                af[mt][1] = Hpu[(r0 + 8) * ENC_HP_LD + k0 + rr];
                af[mt][2] = Hpu[r0 * ENC_HP_LD + k0 + rr + 4];
                af[mt][3] = Hpu[(r0 + 8) * ENC_HP_LD + k0 + rr + 4];
            }
            unsigned bf[4][2];
            #pragma unroll
            for (int nt = 0; nt < 4; ++nt) {
                int n = wn * 32 + nt * 8 + qp;
                bf[nt][0] = sWu[(k0 + rr) * ENC_SW_LD + n];
                bf[nt][1] = sWu[(k0 + 4 + rr) * ENC_SW_LD + n];
            }
            #pragma unroll
            for (int mt = 0; mt < 2; ++mt)
                #pragma unroll
                for (int nt = 0; nt < 4; ++nt)
                    mma_tf32(acc[mt][nt], af[mt], bf[nt]);
        }

        #pragma unroll
        for (int nt = 0; nt < 4; ++nt) {
            int n = wn * 32 + nt * 8 + 2 * rr;
            float bv0 = b3[nc * 128 + n];
            float bv1 = b3[nc * 128 + n + 1];
            float m0 = 0.f, m1 = 0.f;
            #pragma unroll
            for (int mt = 0; mt < 2; ++mt) {
                float* d = acc[mt][nt];
                m0 = fmaxf(m0, fmaxf(d[0] + bv0, d[2] + bv0));
                m1 = fmaxf(m1, fmaxf(d[1] + bv1, d[3] + bv1));
            }
            #pragma unroll
            for (int s = 4; s < 32; s <<= 1) {
                m0 = fmaxf(m0, __shfl_xor_sync(0xffffffffu, m0, s));
                m1 = fmaxf(m1, __shfl_xor_sync(0xffffffffu, m1, s));
            }
            if (qp == 0) {
                sRed[wm * 128 + n]     = m0;
                sRed[wm * 128 + n + 1] = m1;
            }
        }
        __syncthreads();
        if (tid < 128) {
            float m = fmaxf(fmaxf(sRed[tid], sRed[128 + tid]),
                            fmaxf(sRed[256 + tid], sRed[384 + tid]));
            atomicMax((int*)&g_feat[b * 512 + nc * 128 + tid], __float_as_int(m));
        }
        __syncthreads();
    }
}

// ---------------------------------------------------------------------------
// Head MLP (identical to R9 passing version)
// ---------------------------------------------------------------------------
__global__ void __launch_bounds__(512) head_kernel(
    const float* __restrict__ w1, const float* __restrict__ b1,
    const float* __restrict__ w2, const float* __restrict__ b2,
    const float* __restrict__ w3, const float* __restrict__ b3)
{
    __shared__ float sh[512];
    __shared__ float pp[512];
    __shared__ float s1[256];
    __shared__ float s2[128];
    int b = blockIdx.x, tid = threadIdx.x;
    sh[tid] = g_feat[b * 512 + tid];
    __syncthreads();
    {
        int j = tid & 255, half = tid >> 8, k0 = half * 256;
        const float* wp = w1 + (size_t)k0 * 256 + j;
        float a0 = 0, a1 = 0, a2 = 0, a3 = 0;
        #pragma unroll 8
        for (int k = 0; k < 256; k += 4) {
            a0 += sh[k0 + k]     * wp[(size_t)k * 256];
            a1 += sh[k0 + k + 1] * wp[(size_t)(k + 1) * 256];
            a2 += sh[k0 + k + 2] * wp[(size_t)(k + 2) * 256];
            a3 += sh[k0 + k + 3] * wp[(size_t)(k + 3) * 256];
        }
        pp[tid] = (a0 + a1) + (a2 + a3);
    }
    __syncthreads();
    if (tid < 256) s1[tid] = fmaxf(b1[tid] + pp[tid] + pp[tid + 256], 0.f);
    __syncthreads();
    {
        int j = tid & 127, q = tid >> 7, k0 = q * 64;
        const float* wp = w2 + k0 * 128 + j;
        float a0 = 0, a1 = 0;
        #pragma unroll 8
        for (int k = 0; k < 64; k += 2) {
            a0 += s1[k0 + k]     * wp[k * 128];
            a1 += s1[k0 + k + 1] * wp[(k + 1) * 128];
        }
        pp[tid] = a0 + a1;
    }
    __syncthreads();
    if (tid < 128) s2[tid] = fmaxf(b2[tid] + pp[tid] + pp[tid + 128] + pp[tid + 256] + pp[tid + 384], 0.f);
    __syncthreads();
    {
        int j = tid & 255, half = tid >> 8, k0 = half * 64;
        const float* wp = w3 + k0 * 256 + j;
        float a0 = 0, a1 = 0;
        #pragma unroll 8
        for (int k = 0; k < 64; k += 2) {
            a0 += s2[k0 + k]     * wp[k * 256];
            a1 += s2[k0 + k + 1] * wp[(k + 1) * 256];
        }
        pp[tid] = a0 + a1;
    }
    __syncthreads();
    if (tid < 256) g_gruh[b * HID + tid] = b3[tid] + pp[tid] + pp[tid + 256];
}

// ---------------------------------------------------------------------------
// GRU rollout v6: same pair topology as R7/R9, but 768 threads (24 warps/SM)
//  - GEMM: 96 j-groups x 8 k-slices of 32; per-thread work halved
//  - same W traffic (threads partition jxk exactly once)
// ---------------------------------------------------------------------------
#define GRU_SMEM_FLOATS 42792

__global__ void __launch_bounds__(768) gru_kernel(
    const float* __restrict__ Wih, const float* __restrict__ bih, const float* __restrict__ bhh,
    const float* __restrict__ ow1, const float* __restrict__ ob1,
    const float* __restrict__ ow2, const float* __restrict__ ob2,
    const float* __restrict__ ow3, const float* __restrict__ ob3,
    const int* __restrict__ horizon_p, float* __restrict__ out, int out_size)
{
    extern __shared__ float sm[];
    float* s_Wih  = sm;                   // 4608
    float* s_bih  = s_Wih + 4608;         // 768
    float* s_bhh  = s_bih + 768;          // 768
    float* s_w1   = s_bhh + 768;          // 16384
    float* s_w2   = s_w1 + 16384;         // 4096
    float* s_w3   = s_w2 + 4096;          // 384
    float* s_b1   = s_w3 + 384;           // 64
    float* s_b2   = s_b1 + 64;            // 64
    float* s_b3   = s_b2 + 64;            // 8
    float* s_h    = s_b3 + 8;             // 1024
    float* s_x    = s_h + 1024;           // 32
    float* s_gh   = s_x + 32;             // 3072
    float* s_part = s_gh + 3072;          // 10752 (7 slices x 96 jg x 16)
    float* s_p1   = s_part + 10752;       // 512 (2 rows x 4 kq x 64)
    float* s_o1   = s_p1 + 512;           // 128
    float* s_o2   = s_o1 + 128;           // 128

    const int tid     = threadIdx.x;
    const int bid     = blockIdx.x;
    const int pairid  = bid >> 1;
    const int half    = bid & 1;
    const int partner = bid ^ 1;
    const int b0      = pairid * 4;

    for (int i = tid; i < 4608;  i += 768) s_Wih[i] = Wih[i];
    for (int i = tid; i < 768;   i += 768) { s_bih[i] = bih[i]; s_bhh[i] = bhh[i]; }
    for (int i = tid; i < 16384; i += 768) s_w1[i] = ow1[i];
    for (int i = tid; i < 4096;  i += 768) s_w2[i] = ow2[i];
    if (tid < 384) s_w3[tid] = ow3[tid];
    if (tid < 64) { s_b1[tid] = ob1[tid]; s_b2[tid] = ob2[tid]; }
    if (tid < 6)  s_b3[tid] = ob3[tid];
    for (int i = tid; i < 1024; i += 768) {
        int r = i >> 8, k = i & 255;
        s_h[i] = g_gruh[(b0 + r) * HID + k];
    }
    if (tid < 32) s_x[tid] = 0.f;
    __syncthreads();

    int T = 50;
    if (horizon_p) {
        int v = *horizon_p;
        if (v > 0 && v <= 1000000) T = v;
        else {
            float fv = __int_as_float(v);
            if (fv > 0.f && fv <= 1000000.f) T = (int)fv;
        }
    }
    const int off2 = out_size >> 1;

    const int jg   = tid % 96;            // 96 j-groups of 4 cols
    const int ks   = tid / 96;            // 8 k-slices of 32
    const int k0   = ks * 32;
    const int jcol = half * 384 + jg * 4;
    const float* Wcol = g_WhhT + jcol;

    for (int t = 0; t < T; ++t) {
        const int par = t & 1;
        float* pay_out = &g_pay[par][bid][0];
        const float* pay_in = &g_pay[par][partner][0];

        // ---- gh-half GEMM: 4 rows x 4 cols per thread over 32 k ----
        float acc[4][4];
        #pragma unroll
        for (int r = 0; r < 4; ++r)
            #pragma unroll
            for (int c = 0; c < 4; ++c) acc[r][c] = 0.f;

        #pragma unroll 2
        for (int kk = 0; kk < 32; kk += 4) {
            float4 h0 = *(float4*)&s_h[0 * 256 + k0 + kk];
            float4 h1 = *(float4*)&s_h[1 * 256 + k0 + kk];
            float4 h2 = *(float4*)&s_h[2 * 256 + k0 + kk];
            float4 h3 = *(float4*)&s_h[3 * 256 + k0 + kk];
            const float* wb = Wcol + (size_t)(k0 + kk) * 768;
            #pragma unroll
            for (int q = 0; q < 4; ++q) {
                float4 w = *(const float4*)(wb + (size_t)q * 768);
                float a0 = (q == 0) ? h0.x : (q == 1) ? h0.y : (q == 2) ? h0.z : h0.w;
                float a1 = (q == 0) ? h1.x : (q == 1) ? h1.y : (q == 2) ? h1.z : h1.w;
                float a2 = (q == 0) ? h2.x : (q == 1) ? h2.y : (q == 2) ? h2.z : h2.w;
                float a3 = (q == 0) ? h3.x : (q == 1) ? h3.y : (q == 2) ? h3.z : h3.w;
                acc[0][0] += a0*w.x; acc[0][1] += a0*w.y; acc[0][2] += a0*w.z; acc[0][3] += a0*w.w;
                acc[1][0] += a1*w.x; acc[1][1] += a1*w.y; acc[1][2] += a1*w.z; acc[1][3] += a1*w.w;
                acc[2][0] += a2*w.x; acc[2][1] += a2*w.y; acc[2][2] += a2*w.z; acc[2][3] += a2*w.w;
                acc[3][0] += a3*w.x; acc[3][1] += a3*w.y; acc[3][2] += a3*w.z; acc[3][3] += a3*w.w;
            }
        }

        // ---- reduce 8 k-slices ----
        if (ks > 0) {
            float* p = &s_part[((ks - 1) * 96 + jg) * 16];
            #pragma unroll
            for (int r = 0; r < 4; ++r)
                *(float4*)(p + r * 4) = make_float4(acc[r][0], acc[r][1], acc[r][2], acc[r][3]);
        }
        __syncthreads();
        if (ks == 0) {
            #pragma unroll
            for (int s = 0; s < 7; ++s) {
                const float* p = &s_part[(s * 96 + jg) * 16];
                #pragma unroll
                for (int r = 0; r < 4; ++r) {
                    float4 v = *(const float4*)(p + r * 4);
                    acc[r][0] += v.x; acc[r][1] += v.y; acc[r][2] += v.z; acc[r][3] += v.w;
                }
            }
            #pragma unroll
            for (int r = 0; r < 4; ++r) {
                float4 v = make_float4(acc[r][0], acc[r][1], acc[r][2], acc[r][3]);
                *(float4*)&s_gh[r * 768 + jcol] = v;
                *(float4*)&pay_out[r * 384 + jg * 4] = v;
            }
        }
        if (tid < 12) {
            int rl = tid / 6, a = tid % 6;
            pay_out[1536 + tid] = s_x[(half * 2 + rl) * 8 + a];
        }
        __threadfence();
        __syncthreads();
        if (tid == 0) {
            atomicExch(&g_flag[bid], t + 1);
            volatile int* f = &g_flag[partner];
            while (*f < t + 1) {}
            __threadfence();
        }
        __syncthreads();

        // ---- pull partner half into s_gh + partner x ----
        if (tid < 384) {
            int rr = tid / 96, off = (tid % 96) * 4;
            float4 v = __ldcg((const float4*)&pay_in[rr * 384 + off]);
            *(float4*)&s_gh[rr * 768 + (half ^ 1) * 384 + off] = v;
        }
        if (tid < 12) {
            int rl = tid / 6, a = tid % 6;
            s_x[((half ^ 1) * 2 + rl) * 8 + a] = __ldcg(&pay_in[1536 + tid]);
        }
        __syncthreads();

        // ---- gates + h update (all 4 rows, redundant across the pair) ----
        #pragma unroll
        for (int it = 0; it < 2; ++it) {
            int item = tid + it * 768;
            if (item < 1024) {
                int r = item >> 8, kk = item & 255;
                float x0 = s_x[r*8+0], x1 = s_x[r*8+1], x2 = s_x[r*8+2];
                float x3 = s_x[r*8+3], x4 = s_x[r*8+4], x5 = s_x[r*8+5];
                const float* wr = s_Wih + kk * 6;
                const float* wz = s_Wih + (256 + kk) * 6;
                const float* wn = s_Wih + (512 + kk) * 6;
                float gir = s_bih[kk]       + x0*wr[0]+x1*wr[1]+x2*wr[2]+x3*wr[3]+x4*wr[4]+x5*wr[5];
                float giz = s_bih[256 + kk] + x0*wz[0]+x1*wz[1]+x2*wz[2]+x3*wz[3]+x4*wz[4]+x5*wz[5];
                float gin = s_bih[512 + kk] + x0*wn[0]+x1*wn[1]+x2*wn[2]+x3*wn[3]+x4*wn[4]+x5*wn[5];
                float rr = sigf(gir + s_gh[r*768 + kk] + s_bhh[kk]);
                float zz = sigf(giz + s_gh[r*768 + 256 + kk] + s_bhh[256 + kk]);
                float nn = tanhfast(gin + rr * (s_gh[r*768 + 512 + kk] + s_bhh[512 + kk]));
                s_h[r*256 + kk] = (1.f - zz) * nn + zz * s_h[r*256 + kk];
            }
        }
        __syncthreads();

        // ---- out MLP for own 2 rows: 256 -> 64 -> 64 -> 6 (4-way k-split) ----
        if (tid < 512) {
            int rl = tid >> 8, kq = (tid >> 6) & 3, j = tid & 63;
            const float* hb = s_h + (half * 2 + rl) * 256 + kq * 64;
            const float* wp = s_w1 + (kq * 64) * 64 + j;
            float a0 = 0, a1 = 0;
            #pragma unroll 8
            for (int k = 0; k < 64; k += 2) {
                a0 += hb[k]     * wp[k * 64];
                a1 += hb[k + 1] * wp[(k + 1) * 64];
            }
            s_p1[(rl * 4 + kq) * 64 + j] = a0 + a1;
        }
        __syncthreads();
        if (tid < 128) {
            int rl = tid >> 6, j = tid & 63;
            const float* p = s_p1 + rl * 256 + j;
            s_o1[tid] = fmaxf(s_b1[j] + (p[0] + p[64]) + (p[128] + p[192]), 0.f);
        }
        __syncthreads();
        if (tid < 128) {
            int rl = tid >> 6, j = tid & 63;
            float a0 = 0, a1 = 0;
            #pragma unroll 8
            for (int k = 0; k < 64; k += 2) {
                a0 += s_o1[rl*64 + k]     * s_w2[k * 64 + j];
                a1 += s_o1[rl*64 + k + 1] * s_w2[(k + 1) * 64 + j];
            }
            s_o2[tid] = fmaxf(s_b2[j] + a0 + a1, 0.f);
        }
        __syncthreads();
        if (tid < 12) {
            int rl = tid / 6, a = tid % 6;
            float d0 = 0, d1 = 0;
            #pragma unroll 8
            for (int k = 0; k < 64; k += 2) {
                d0 += s_o2[rl*64 + k]     * s_w3[k * 6 + a];
                d1 += s_o2[rl*64 + k + 1] * s_w3[(k + 1) * 6 + a];
            }
            float d = s_b3[a] + d0 + d1;
            int rloc = half * 2 + rl;
            float xn = s_x[rloc * 8 + a] + d;
            s_x[rloc * 8 + a] = xn;
            int b = b0 + rloc;
            size_t o = ((size_t)b * T + t) * 6 + a;
            out[o] = d;
            out[off2 + o] = xn;
        }
        __syncthreads();
    }
}

// ---------------------------------------------------------------------------
// launch
// ---------------------------------------------------------------------------
extern "C" void kernel_launch(void* const* d_in, const int* in_sizes, int n_in,
                              void* d_out, int out_size)
{
    int hpos = -1;
    for (int i = 0; i < n_in; ++i) if (in_sizes[i] == 1) hpos = i;

    const float* ins[23];
    int j = 0;
    for (int i = 0; i < n_in && j < 23; ++i) {
        if (i == hpos) continue;
        ins[j++] = (const float*)d_in[i];
    }
    const int* hp = (hpos >= 0) ? (const int*)d_in[hpos] : nullptr;

    // ins: 0 data | 1 enc_w1 2 enc_b1 3 enc_w2 4 enc_b2 5 enc_w3 6 enc_b3
    //      7 mlp_w1 8 mlp_b1 9 mlp_w2 10 mlp_b2 11 mlp_w3 12 mlp_b3
    //      13 W_ih 14 W_hh 15 b_ih 16 b_hh
    //      17 out_w1 18 out_b1 19 out_w2 20 out_b2 21 out_w3 22 out_b3

    const int enc_smem = ENC_SMEM_FLOATS * 4;
    const int gru_smem = GRU_SMEM_FLOATS * 4;
    cudaFuncSetAttribute(enc_kernel, cudaFuncAttributeMaxDynamicSharedMemorySize, enc_smem);
    cudaFuncSetAttribute(gru_kernel, cudaFuncAttributeMaxDynamicSharedMemorySize, gru_smem);

    prep_kernel<<<1569, 256>>>(ins[14], ins[5], ins[3]);
    enc_kernel<<<dim3(8, 256), 512, enc_smem>>>(ins[0], ins[1], ins[2], ins[4], ins[6]);
    head_kernel<<<256, 512>>>(ins[7], ins[8], ins[9], ins[10], ins[11], ins[12]);
    gru_kernel<<<GRU_BLOCKS, 768, gru_smem>>>(ins[13], ins[15], ins[16],
                                              ins[17], ins[18], ins[19], ins[20], ins[21], ins[22],
                                              hp, (float*)d_out, out_size);
}

// round 11
// speedup vs baseline: 2.1739x; 1.0447x over previous
#include <cuda_runtime.h>
#include <cuda_bf16.h>
#include <cstdint>
#include <cstddef>

// ---------------------------------------------------------------------------
// Problem constants
// ---------------------------------------------------------------------------
#define BATCH   256
#define NPTS    1024
#define HID     256
#define ACT     6
#define GRU_BLOCKS 128

// device scratch
__device__ float g_feat[BATCH * 512];
__device__ float g_gruh[BATCH * HID];
__device__ float g_WhhT[HID * 768];
__device__ unsigned g_W3tf[4 * 128 * 128];   // tf32 image, [nc][k][n]
__device__ unsigned g_W2tf[64 * 128];        // tf32 image of W2 [k][j]
// GRU pair-exchange payload: [parity][block][4*384 gh + 16 x] + flags
__device__ float g_pay[2][GRU_BLOCKS][1552];
__device__ int   g_flag[GRU_BLOCKS];

// ---------------------------------------------------------------------------
// helpers
// ---------------------------------------------------------------------------
__device__ __forceinline__ unsigned f2tf(float x) {
    unsigned u; asm("cvt.rna.tf32.f32 %0, %1;" : "=r"(u) : "f"(x)); return u;
}

__device__ __forceinline__ void mma_tf32(float* d, const unsigned* a, const unsigned* b) {
    asm volatile(
        "mma.sync.aligned.m16n8k8.row.col.f32.tf32.tf32.f32 "
        "{%0,%1,%2,%3}, {%4,%5,%6,%7}, {%8,%9}, {%0,%1,%2,%3};\n"
        : "+f"(d[0]), "+f"(d[1]), "+f"(d[2]), "+f"(d[3])
        : "r"(a[0]), "r"(a[1]), "r"(a[2]), "r"(a[3]), "r"(b[0]), "r"(b[1]));
}

__device__ __forceinline__ void cp16(uint32_t dst_smem, const void* src) {
    asm volatile("cp.async.cg.shared.global [%0], [%1], 16;" :: "r"(dst_smem), "l"(src));
}
#define CP_COMMIT() asm volatile("cp.async.commit_group;" ::: "memory")
#define CP_WAIT1()  asm volatile("cp.async.wait_group 1;" ::: "memory")
#define CP_WAIT0()  asm volatile("cp.async.wait_group 0;" ::: "memory")

__device__ __forceinline__ float sigf(float x) { return 1.f / (1.f + __expf(-x)); }
__device__ __forceinline__ float tanhfast(float x) { return 2.f / (1.f + __expf(-2.f * x)) - 1.f; }

// ---------------------------------------------------------------------------
// fused prep kernel: zero_feat | Whh transpose | W3 tf32 | W2 tf32 | flags
// ---------------------------------------------------------------------------
__global__ void prep_kernel(const float* __restrict__ Whh,
                            const float* __restrict__ w3,
                            const float* __restrict__ w2) {
    int idx = blockIdx.x * 256 + threadIdx.x;
    if (idx < 131072) { g_feat[idx] = 0.f; return; }
    idx -= 131072;
    if (idx < 196608) {
        int k = idx / 768, j = idx - k * 768;
        g_WhhT[idx] = Whh[j * 256 + k];
        return;
    }
    idx -= 196608;
    if (idx < 65536) {
        int nc = idx >> 14, r = idx & 16383;
        int k = r >> 7, n = r & 127;
        g_W3tf[idx] = f2tf(w3[(size_t)k * 512 + nc * 128 + n]);
        return;
    }
    idx -= 65536;
    if (idx < 8192) { g_W2tf[idx] = f2tf(w2[idx]); return; }
    idx -= 8192;
    if (idx < GRU_BLOCKS) g_flag[idx] = 0;
}

// ---------------------------------------------------------------------------
// Fused PointNet encoder: 3->64 (fp32) -> 128 (tf32 mma) -> 512 (tf32 mma)
// grid (8 chunks, 256 batches), 512 threads; W3 staged via cp.async dbl-buffer
// ---------------------------------------------------------------------------
#define ENC_HP_LD 132
#define ENC_SW_LD 136
#define ENC_A2_LD 68
// Hp 16896 | buf0 17408 | buf1 17408 | sRed 512
#define ENC_SMEM_FLOATS (16896 + 17408 + 17408 + 512)

__global__ void __launch_bounds__(512) enc_kernel(
    const float* __restrict__ data,
    const float* __restrict__ w1, const float* __restrict__ b1,
    const float* __restrict__ b2, const float* __restrict__ b3)
{
    extern __shared__ float sm[];
    float* Hp   = sm;
    float* buf0 = sm + 16896;
    float* buf1 = buf0 + 17408;
    float* sRed = buf1 + 17408;
    __shared__ float sPts[128 * 3];

    const int tid   = threadIdx.x;
    const int b     = blockIdx.y;
    const int chunk = blockIdx.x;

    unsigned* A2 = (unsigned*)buf0;            // layer-1 out [i][68] tf32
    unsigned* B2 = (unsigned*)(buf0 + 8704);   // W2 [k][136] tf32

    float* bufs[2] = {buf0, buf1};
    uint32_t bufaddr[2];
    bufaddr[0] = (uint32_t)__cvta_generic_to_shared(buf0);
    bufaddr[1] = (uint32_t)__cvta_generic_to_shared(buf1);

    // ---- prefetch W3 chunk 0 into buf1 (async) ----
    {
        const float* src = (const float*)(g_W3tf);
        for (int i = tid * 4; i < 16384; i += 2048) {
            int k = i >> 7, n = i & 127;
            cp16(bufaddr[1] + (k * ENC_SW_LD + n) * 4, src + i);
        }
        CP_COMMIT();
    }

    // ---- stage points + W2 (tf32 image) ----
    const float* dptr = data + (size_t)(b * NPTS + chunk * 128) * 3;
    if (tid < 384) sPts[tid] = dptr[tid];
    for (int idx = tid; idx < 8192; idx += 512) {
        int k = idx >> 7, j = idx & 127;
        B2[k * ENC_SW_LD + j] = g_W2tf[idx];
    }
    __syncthreads();

    // ---- layer 1: A2[i][k] = tf32(relu(p . w1col + b1)) ----
    #pragma unroll
    for (int it = 0; it < 16; ++it) {
        int idx = tid + it * 512;
        int k = idx >> 7, i = idx & 127;
        float v = b1[k] + sPts[i*3] * w1[k] + sPts[i*3+1] * w1[64 + k] + sPts[i*3+2] * w1[128 + k];
        A2[i * ENC_A2_LD + k] = f2tf(fmaxf(v, 0.f));
    }
    __syncthreads();

    const int lane = tid & 31, wrp = tid >> 5;
    const int wm = wrp & 3, wn = wrp >> 2;
    const int qp = lane >> 2, rr = lane & 3;
    unsigned* Hpu = (unsigned*)Hp;

    // ---- layer 2 via tf32 mma: M=128, N=128, K=64 -> Hp tf32 ----
    {
        float acc[2][4][4];
        #pragma unroll
        for (int mt = 0; mt < 2; ++mt)
            #pragma unroll
            for (int nt = 0; nt < 4; ++nt)
                #pragma unroll
                for (int q = 0; q < 4; ++q) acc[mt][nt][q] = 0.f;

        #pragma unroll 2
        for (int ks = 0; ks < 8; ++ks) {
            int k0 = ks * 8;
            unsigned af[2][4];
            #pragma unroll
            for (int mt = 0; mt < 2; ++mt) {
                int r0 = wm * 32 + mt * 16 + qp;
                af[mt][0] = A2[r0 * ENC_A2_LD + k0 + rr];
                af[mt][1] = A2[(r0 + 8) * ENC_A2_LD + k0 + rr];
                af[mt][2] = A2[r0 * ENC_A2_LD + k0 + rr + 4];
                af[mt][3] = A2[(r0 + 8) * ENC_A2_LD + k0 + rr + 4];
            }
            unsigned bf[4][2];
            #pragma unroll
            for (int nt = 0; nt < 4; ++nt) {
                int n = wn * 32 + nt * 8 + qp;
                bf[nt][0] = B2[(k0 + rr) * ENC_SW_LD + n];
                bf[nt][1] = B2[(k0 + 4 + rr) * ENC_SW_LD + n];
            }
            #pragma unroll
            for (int mt = 0; mt < 2; ++mt)
                #pragma unroll
                for (int nt = 0; nt < 4; ++nt)
                    mma_tf32(acc[mt][nt], af[mt], bf[nt]);
        }

        #pragma unroll
        for (int mt = 0; mt < 2; ++mt) {
            int r0 = wm * 32 + mt * 16 + qp;
            #pragma unroll
            for (int nt = 0; nt < 4; ++nt) {
                int c0 = wn * 32 + nt * 8 + 2 * rr;
                float bv0 = b2[c0], bv1 = b2[c0 + 1];
                float* d = acc[mt][nt];
                unsigned u0 = f2tf(fmaxf(d[0] + bv0, 0.f));
                unsigned u1 = f2tf(fmaxf(d[1] + bv1, 0.f));
                unsigned u2 = f2tf(fmaxf(d[2] + bv0, 0.f));
                unsigned u3 = f2tf(fmaxf(d[3] + bv1, 0.f));
                *(uint2*)(Hpu + r0 * ENC_HP_LD + c0)       = make_uint2(u0, u1);
                *(uint2*)(Hpu + (r0 + 8) * ENC_HP_LD + c0) = make_uint2(u2, u3);
            }
        }
    }
    __syncthreads();   // buf0 (A2/B2) now free for cp.async reuse

    // ---- layer 3: tf32 mma, 4 N-chunks, double-buffered W3 ----
    for (int nc = 0; nc < 4; ++nc) {
        // issue prefetch of chunk nc+1 into the buffer not read this iter
        if (nc < 3) {
            const float* src = (const float*)(g_W3tf + (nc + 1) * 16384);
            uint32_t da = bufaddr[nc & 1];
            for (int i = tid * 4; i < 16384; i += 2048) {
                int k = i >> 7, n = i & 127;
                cp16(da + (k * ENC_SW_LD + n) * 4, src + i);
            }
            CP_COMMIT();
            CP_WAIT1();     // chunk nc has landed
        } else {
            CP_WAIT0();
        }
        __syncthreads();

        unsigned* sWu = (unsigned*)bufs[(nc + 1) & 1];

        float acc[2][4][4];
        #pragma unroll
        for (int mt = 0; mt < 2; ++mt)
            #pragma unroll
            for (int nt = 0; nt < 4; ++nt)
                #pragma unroll
                for (int q = 0; q < 4; ++q) acc[mt][nt][q] = 0.f;

        #pragma unroll 2
        for (int ks = 0; ks < 16; ++ks) {
            int k0 = ks * 8;
            unsigned af[2][4];
            #pragma unroll
            for (int mt = 0; mt < 2; ++mt) {
                int r0 = wm * 32 + mt * 16 + qp;
                af[mt][0] = Hpu[r0 * ENC_HP_LD + k0 + rr];
                af[mt][1] = Hpu[(r0 + 8) * ENC_HP_LD + k0 + rr];
                af[mt][2] = Hpu[r0 * ENC_HP_LD + k0 + rr + 4];
                af[mt][3] = Hpu[(r0 + 8) * ENC_HP_LD + k0 + rr + 4];
            }
            unsigned bf[4][2];
            #pragma unroll
            for (int nt = 0; nt < 4; ++nt) {
                int n = wn * 32 + nt * 8 + qp;
                bf[nt][0] = sWu[(k0 + rr) * ENC_SW_LD + n];
                bf[nt][1] = sWu[(k0 + 4 + rr) * ENC_SW_LD + n];
            }
            #pragma unroll
            for (int mt = 0; mt < 2; ++mt)
                #pragma unroll
                for (int nt = 0; nt < 4; ++nt)
                    mma_tf32(acc[mt][nt], af[mt], bf[nt]);
        }

        #pragma unroll
        for (int nt = 0; nt < 4; ++nt) {
            int n = wn * 32 + nt * 8 + 2 * rr;
            float bv0 = b3[nc * 128 + n];
            float bv1 = b3[nc * 128 + n + 1];
            float m0 = 0.f, m1 = 0.f;
            #pragma unroll
            for (int mt = 0; mt < 2; ++mt) {
                float* d = acc[mt][nt];
                m0 = fmaxf(m0, fmaxf(d[0] + bv0, d[2] + bv0));
                m1 = fmaxf(m1, fmaxf(d[1] + bv1, d[3] + bv1));
            }
            #pragma unroll
            for (int s = 4; s < 32; s <<= 1) {
                m0 = fmaxf(m0, __shfl_xor_sync(0xffffffffu, m0, s));
                m1 = fmaxf(m1, __shfl_xor_sync(0xffffffffu, m1, s));
            }
            if (qp == 0) {
                sRed[wm * 128 + n]     = m0;
                sRed[wm * 128 + n + 1] = m1;
            }
        }
        __syncthreads();
        if (tid < 128) {
            float m = fmaxf(fmaxf(sRed[tid], sRed[128 + tid]),
                            fmaxf(sRed[256 + tid], sRed[384 + tid]));
            atomicMax((int*)&g_feat[b * 512 + nc * 128 + tid], __float_as_int(m));
        }
        __syncthreads();
    }
}

// ---------------------------------------------------------------------------
// Head MLP (identical to R10 passing version)
// ---------------------------------------------------------------------------
__global__ void __launch_bounds__(512) head_kernel(
    const float* __restrict__ w1, const float* __restrict__ b1,
    const float* __restrict__ w2, const float* __restrict__ b2,
    const float* __restrict__ w3, const float* __restrict__ b3)
{
    __shared__ float sh[512];
    __shared__ float pp[512];
    __shared__ float s1[256];
    __shared__ float s2[128];
    int b = blockIdx.x, tid = threadIdx.x;
    sh[tid] = g_feat[b * 512 + tid];
    __syncthreads();
    {
        int j = tid & 255, half = tid >> 8, k0 = half * 256;
        const float* wp = w1 + (size_t)k0 * 256 + j;
        float a0 = 0, a1 = 0, a2 = 0, a3 = 0;
        #pragma unroll 8
        for (int k = 0; k < 256; k += 4) {
            a0 += sh[k0 + k]     * wp[(size_t)k * 256];
            a1 += sh[k0 + k + 1] * wp[(size_t)(k + 1) * 256];
            a2 += sh[k0 + k + 2] * wp[(size_t)(k + 2) * 256];
            a3 += sh[k0 + k + 3] * wp[(size_t)(k + 3) * 256];
        }
        pp[tid] = (a0 + a1) + (a2 + a3);
    }
    __syncthreads();
    if (tid < 256) s1[tid] = fmaxf(b1[tid] + pp[tid] + pp[tid + 256], 0.f);
    __syncthreads();
    {
        int j = tid & 127, q = tid >> 7, k0 = q * 64;
        const float* wp = w2 + k0 * 128 + j;
        float a0 = 0, a1 = 0;
        #pragma unroll 8
        for (int k = 0; k < 64; k += 2) {
            a0 += s1[k0 + k]     * wp[k * 128];
            a1 += s1[k0 + k + 1] * wp[(k + 1) * 128];
        }
        pp[tid] = a0 + a1;
    }
    __syncthreads();
    if (tid < 128) s2[tid] = fmaxf(b2[tid] + pp[tid] + pp[tid + 128] + pp[tid + 256] + pp[tid + 384], 0.f);
    __syncthreads();
    {
        int j = tid & 255, half = tid >> 8, k0 = half * 64;
        const float* wp = w3 + k0 * 256 + j;
        float a0 = 0, a1 = 0;
        #pragma unroll 8
        for (int k = 0; k < 64; k += 2) {
            a0 += s2[k0 + k]     * wp[k * 256];
            a1 += s2[k0 + k + 1] * wp[(k + 1) * 256];
        }
        pp[tid] = a0 + a1;
    }
    __syncthreads();
    if (tid < 256) g_gruh[b * HID + tid] = b3[tid] + pp[tid] + pp[tid + 256];
}

// ---------------------------------------------------------------------------
// GRU rollout v7: R10 pair topology + parallel slice reduce + acq/rel flags
// 128 blocks x 768 threads
// ---------------------------------------------------------------------------
#define GRU_SMEM_FLOATS 44328

__global__ void __launch_bounds__(768) gru_kernel(
    const float* __restrict__ Wih, const float* __restrict__ bih, const float* __restrict__ bhh,
    const float* __restrict__ ow1, const float* __restrict__ ob1,
    const float* __restrict__ ow2, const float* __restrict__ ob2,
    const float* __restrict__ ow3, const float* __restrict__ ob3,
    const int* __restrict__ horizon_p, float* __restrict__ out, int out_size)
{
    extern __shared__ float sm[];
    float* s_Wih  = sm;                   // 4608
    float* s_bih  = s_Wih + 4608;         // 768
    float* s_bhh  = s_bih + 768;          // 768
    float* s_w1   = s_bhh + 768;          // 16384
    float* s_w2   = s_w1 + 16384;         // 4096
    float* s_w3   = s_w2 + 4096;          // 384
    float* s_b1   = s_w3 + 384;           // 64
    float* s_b2   = s_b1 + 64;            // 64
    float* s_b3   = s_b2 + 64;            // 8
    float* s_h    = s_b3 + 8;             // 1024
    float* s_x    = s_h + 1024;           // 32
    float* s_gh   = s_x + 32;             // 3072
    float* s_part = s_gh + 3072;          // 12288 (8 slices x 96 jg x 16)
    float* s_p1   = s_part + 12288;       // 512
    float* s_o1   = s_p1 + 512;           // 128
    float* s_o2   = s_o1 + 128;           // 128

    const int tid     = threadIdx.x;
    const int bid     = blockIdx.x;
    const int pairid  = bid >> 1;
    const int half    = bid & 1;
    const int partner = bid ^ 1;
    const int b0      = pairid * 4;

    for (int i = tid; i < 4608;  i += 768) s_Wih[i] = Wih[i];
    for (int i = tid; i < 768;   i += 768) { s_bih[i] = bih[i]; s_bhh[i] = bhh[i]; }
    for (int i = tid; i < 16384; i += 768) s_w1[i] = ow1[i];
    for (int i = tid; i < 4096;  i += 768) s_w2[i] = ow2[i];
    if (tid < 384) s_w3[tid] = ow3[tid];
    if (tid < 64) { s_b1[tid] = ob1[tid]; s_b2[tid] = ob2[tid]; }
    if (tid < 6)  s_b3[tid] = ob3[tid];
    for (int i = tid; i < 1024; i += 768) {
        int r = i >> 8, k = i & 255;
        s_h[i] = g_gruh[(b0 + r) * HID + k];
    }
    if (tid < 32) s_x[tid] = 0.f;
    __syncthreads();

    int T = 50;
    if (horizon_p) {
        int v = *horizon_p;
        if (v > 0 && v <= 1000000) T = v;
        else {
            float fv = __int_as_float(v);
            if (fv > 0.f && fv <= 1000000.f) T = (int)fv;
        }
    }
    const int off2 = out_size >> 1;

    const int jg   = tid % 96;            // 96 j-groups of 4 cols
    const int ks   = tid / 96;            // 8 k-slices of 32
    const int k0   = ks * 32;
    const int jcol = half * 384 + jg * 4;
    const float* Wcol = g_WhhT + jcol;

    // reduce-phase mapping: tid = jgR*8 + r*2 + cp
    const int jgR = tid >> 3;
    const int rR  = (tid >> 1) & 3;
    const int cpR = tid & 1;

    for (int t = 0; t < T; ++t) {
        const int par = t & 1;
        float* pay_out = &g_pay[par][bid][0];
        const float* pay_in = &g_pay[par][partner][0];

        // ---- gh-half GEMM: 4 rows x 4 cols per thread over 32 k ----
        float acc[4][4];
        #pragma unroll
        for (int r = 0; r < 4; ++r)
            #pragma unroll
            for (int c = 0; c < 4; ++c) acc[r][c] = 0.f;

        #pragma unroll 2
        for (int kk = 0; kk < 32; kk += 4) {
            float4 h0 = *(float4*)&s_h[0 * 256 + k0 + kk];
            float4 h1 = *(float4*)&s_h[1 * 256 + k0 + kk];
            float4 h2 = *(float4*)&s_h[2 * 256 + k0 + kk];
            float4 h3 = *(float4*)&s_h[3 * 256 + k0 + kk];
            const float* wb = Wcol + (size_t)(k0 + kk) * 768;
            #pragma unroll
            for (int q = 0; q < 4; ++q) {
                float4 w = *(const float4*)(wb + (size_t)q * 768);
                float a0 = (q == 0) ? h0.x : (q == 1) ? h0.y : (q == 2) ? h0.z : h0.w;
                float a1 = (q == 0) ? h1.x : (q == 1) ? h1.y : (q == 2) ? h1.z : h1.w;
                float a2 = (q == 0) ? h2.x : (q == 1) ? h2.y : (q == 2) ? h2.z : h2.w;
                float a3 = (q == 0) ? h3.x : (q == 1) ? h3.y : (q == 2) ? h3.z : h3.w;
                acc[0][0] += a0*w.x; acc[0][1] += a0*w.y; acc[0][2] += a0*w.z; acc[0][3] += a0*w.w;
                acc[1][0] += a1*w.x; acc[1][1] += a1*w.y; acc[1][2] += a1*w.z; acc[1][3] += a1*w.w;
                acc[2][0] += a2*w.x; acc[2][1] += a2*w.y; acc[2][2] += a2*w.z; acc[2][3] += a2*w.w;
                acc[3][0] += a3*w.x; acc[3][1] += a3*w.y; acc[3][2] += a3*w.z; acc[3][3] += a3*w.w;
            }
        }

        // ---- store all partials, then fully parallel reduce ----
        {
            float* p = &s_part[(ks * 96 + jg) * 16];
            #pragma unroll
            for (int r = 0; r < 4; ++r)
                *(float4*)(p + r * 4) = make_float4(acc[r][0], acc[r][1], acc[r][2], acc[r][3]);
        }
        __syncthreads();
        {
            float sx = 0.f, sy = 0.f;
            #pragma unroll
            for (int s8 = 0; s8 < 8; ++s8) {
                float2 v = *(float2*)&s_part[(s8 * 96 + jgR) * 16 + rR * 4 + cpR * 2];
                sx += v.x; sy += v.y;
            }
            float2 res = make_float2(sx, sy);
            int jloc = jgR * 4 + cpR * 2;
            *(float2*)&s_gh[rR * 768 + half * 384 + jloc] = res;
            *(float2*)&pay_out[rR * 384 + jloc] = res;
        }
        if (tid < 12) {
            int rl = tid / 6, a = tid % 6;
            pay_out[1536 + tid] = s_x[(half * 2 + rl) * 8 + a];
        }
        __syncthreads();
        if (tid == 0) {
            asm volatile("fence.acq_rel.gpu;" ::: "memory");
            atomicExch(&g_flag[bid], t + 1);
            int v;
            do {
                asm volatile("ld.acquire.gpu.global.b32 %0, [%1];"
                             : "=r"(v) : "l"(&g_flag[partner]) : "memory");
            } while (v < t + 1);
        }
        __syncthreads();

        // ---- pull partner half into s_gh + partner x ----
        if (tid < 384) {
            int rr = tid / 96, off = (tid % 96) * 4;
            float4 v = __ldcg((const float4*)&pay_in[rr * 384 + off]);
            *(float4*)&s_gh[rr * 768 + (half ^ 1) * 384 + off] = v;
        }
        if (tid < 12) {
            int rl = tid / 6, a = tid % 6;
            s_x[((half ^ 1) * 2 + rl) * 8 + a] = __ldcg(&pay_in[1536 + tid]);
        }
        __syncthreads();

        // ---- gates + h update (all 4 rows, redundant across the pair) ----
        #pragma unroll
        for (int it = 0; it < 2; ++it) {
            int item = tid + it * 768;
            if (item < 1024) {
                int r = item >> 8, kk = item & 255;
                float x0 = s_x[r*8+0], x1 = s_x[r*8+1], x2 = s_x[r*8+2];
                float x3 = s_x[r*8+3], x4 = s_x[r*8+4], x5 = s_x[r*8+5];
                const float* wr = s_Wih + kk * 6;
                const float* wz = s_Wih + (256 + kk) * 6;
                const float* wn = s_Wih + (512 + kk) * 6;
                float gir = s_bih[kk]       + x0*wr[0]+x1*wr[1]+x2*wr[2]+x3*wr[3]+x4*wr[4]+x5*wr[5];
                float giz = s_bih[256 + kk] + x0*wz[0]+x1*wz[1]+x2*wz[2]+x3*wz[3]+x4*wz[4]+x5*wz[5];
                float gin = s_bih[512 + kk] + x0*wn[0]+x1*wn[1]+x2*wn[2]+x3*wn[3]+x4*wn[4]+x5*wn[5];
                float rr = sigf(gir + s_gh[r*768 + kk] + s_bhh[kk]);
                float zz = sigf(giz + s_gh[r*768 + 256 + kk] + s_bhh[256 + kk]);
                float nn = tanhfast(gin + rr * (s_gh[r*768 + 512 + kk] + s_bhh[512 + kk]));
                s_h[r*256 + kk] = (1.f - zz) * nn + zz * s_h[r*256 + kk];
            }
        }
        __syncthreads();

        // ---- out MLP for own 2 rows: 256 -> 64 -> 64 -> 6 (4-way k-split) ----
        if (tid < 512) {
            int rl = tid >> 8, kq = (tid >> 6) & 3, j = tid & 63;
            const float* hb = s_h + (half * 2 + rl) * 256 + kq * 64;
            const float* wp = s_w1 + (kq * 64) * 64 + j;
            float a0 = 0, a1 = 0;
            #pragma unroll 8
            for (int k = 0; k < 64; k += 2) {
                a0 += hb[k]     * wp[k * 64];
                a1 += hb[k + 1] * wp[(k + 1) * 64];
            }
            s_p1[(rl * 4 + kq) * 64 + j] = a0 + a1;
        }
        __syncthreads();
        if (tid < 128) {
            int rl = tid >> 6, j = tid & 63;
            const float* p = s_p1 + rl * 256 + j;
            s_o1[tid] = fmaxf(s_b1[j] + (p[0] + p[64]) + (p[128] + p[192]), 0.f);
        }
        __syncthreads();
        if (tid < 128) {
            int rl = tid >> 6, j = tid & 63;
            float a0 = 0, a1 = 0;
            #pragma unroll 8
            for (int k = 0; k < 64; k += 2) {
                a0 += s_o1[rl*64 + k]     * s_w2[k * 64 + j];
                a1 += s_o1[rl*64 + k + 1] * s_w2[(k + 1) * 64 + j];
            }
            s_o2[tid] = fmaxf(s_b2[j] + a0 + a1, 0.f);
        }
        __syncthreads();
        if (tid < 12) {
            int rl = tid / 6, a = tid % 6;
            float d0 = 0, d1 = 0;
            #pragma unroll 8
            for (int k = 0; k < 64; k += 2) {
                d0 += s_o2[rl*64 + k]     * s_w3[k * 6 + a];
                d1 += s_o2[rl*64 + k + 1] * s_w3[(k + 1) * 6 + a];
            }
            float d = s_b3[a] + d0 + d1;
            int rloc = half * 2 + rl;
            float xn = s_x[rloc * 8 + a] + d;
            s_x[rloc * 8 + a] = xn;
            int b = b0 + rloc;
            size_t o = ((size_t)b * T + t) * 6 + a;
            out[o] = d;
            out[off2 + o] = xn;
        }
        __syncthreads();
    }
}

// ---------------------------------------------------------------------------
// launch
// ---------------------------------------------------------------------------
extern "C" void kernel_launch(void* const* d_in, const int* in_sizes, int n_in,
                              void* d_out, int out_size)
{
    int hpos = -1;
    for (int i = 0; i < n_in; ++i) if (in_sizes[i] == 1) hpos = i;

    const float* ins[23];
    int j = 0;
    for (int i = 0; i < n_in && j < 23; ++i) {
        if (i == hpos) continue;
        ins[j++] = (const float*)d_in[i];
    }
    const int* hp = (hpos >= 0) ? (const int*)d_in[hpos] : nullptr;

    // ins: 0 data | 1 enc_w1 2 enc_b1 3 enc_w2 4 enc_b2 5 enc_w3 6 enc_b3
    //      7 mlp_w1 8 mlp_b1 9 mlp_w2 10 mlp_b2 11 mlp_w3 12 mlp_b3
    //      13 W_ih 14 W_hh 15 b_ih 16 b_hh
    //      17 out_w1 18 out_b1 19 out_w2 20 out_b2 21 out_w3 22 out_b3

    const int enc_smem = ENC_SMEM_FLOATS * 4;
    const int gru_smem = GRU_SMEM_FLOATS * 4;
    cudaFuncSetAttribute(enc_kernel, cudaFuncAttributeMaxDynamicSharedMemorySize, enc_smem);
    cudaFuncSetAttribute(gru_kernel, cudaFuncAttributeMaxDynamicSharedMemorySize, gru_smem);

    prep_kernel<<<1569, 256>>>(ins[14], ins[5], ins[3]);
    enc_kernel<<<dim3(8, 256), 512, enc_smem>>>(ins[0], ins[1], ins[2], ins[4], ins[6]);
    head_kernel<<<256, 512>>>(ins[7], ins[8], ins[9], ins[10], ins[11], ins[12]);
    gru_kernel<<<GRU_BLOCKS, 768, gru_smem>>>(ins[13], ins[15], ins[16],
                                              ins[17], ins[18], ins[19], ins[20], ins[21], ins[22],
                                              hp, (float*)d_out, out_size);
}